// round 1
// baseline (speedup 1.0000x reference)
#include <cuda_runtime.h>
#include <math.h>

#define T_STEPS 200
#define BATCH   128
#define HID     1024
#define K_IN    120
#define NOUT    12
#define BH      (BATCH*HID)      // 131072
#define NROWS   (T_STEPS*BATCH)  // 25600

// ---------------- static device scratch (no allocations allowed) ------------
__device__ float         g_F[NROWS*HID];       // layer-1 drive, all timesteps (105 MB)
__device__ unsigned char g_s1[NROWS*HID];      // layer-1 spikes, all timesteps (26 MB)
__device__ unsigned char g_sr[2*BH];           // recurrent spikes, ping-pong
__device__ float         g_memr[BH];
__device__ float         g_bbr[BH];
__device__ float         g_racc[BATCH*NOUT];
__device__ float         g_WdT[HID*HID];       // Wd transposed: [h][j]
__device__ float         g_WrT[HID*HID];       // Wr transposed: [h][j]
__device__ float         g_W2T[HID*NOUT];      // W2 transposed: [h][o]
__device__ float         g_ctab[T_STEPS*NOUT]; // c_k[o] = 1 - alpha2^(200-k)
__device__ float         g_csum[NOUT];         // sum_k c_k[o]
__device__ float         g_alphar[HID];        // exp(-1/tau_m_r)
__device__ float         g_ror[HID];           // exp(-1/tau_adp_r)
__device__ float         g_biasr[HID];         // bd + br

// ---------------- prep: transposes ------------------------------------------
__global__ void k_prep_transpose(const float* __restrict__ Wd,
                                 const float* __restrict__ Wr,
                                 const float* __restrict__ W2) {
    int idx = blockIdx.x * blockDim.x + threadIdx.x;
    if (idx < HID*HID) {
        int h = idx / HID, j = idx % HID;
        g_WdT[idx] = Wd[j*HID + h];
        g_WrT[idx] = Wr[j*HID + h];
    }
    if (idx < HID*NOUT) {
        int h = idx / NOUT, o = idx % NOUT;
        g_W2T[idx] = W2[o*HID + h];
    }
}

// ---------------- prep: state init + coefficient tables ---------------------
__global__ void k_prep_state(const float* __restrict__ tau_m2,
                             const float* __restrict__ tau_m_r,
                             const float* __restrict__ tau_adp_r,
                             const float* __restrict__ bd,
                             const float* __restrict__ br) {
    int idx = blockIdx.x * blockDim.x + threadIdx.x;
    if (idx < BH) {
        g_memr[idx] = 0.0f;
        g_bbr[idx]  = 0.01f;
        g_sr[idx]        = 0;
        g_sr[BH + idx]   = 0;
    }
    if (idx < HID) {
        g_alphar[idx] = expf(-1.0f / tau_m_r[idx]);
        g_ror[idx]    = expf(-1.0f / tau_adp_r[idx]);
        g_biasr[idx]  = bd[idx] + br[idx];
    }
    if (idx < BATCH*NOUT) g_racc[idx] = 0.0f;
    if (idx < T_STEPS*NOUT) {
        int k = idx / NOUT, o = idx % NOUT;
        float a2 = expf(-1.0f / tau_m2[o]);
        g_ctab[idx] = 1.0f - powf(a2, (float)(T_STEPS - k));
    }
    if (idx < NOUT) {
        float a2 = expf(-1.0f / tau_m2[idx]);
        float s = 0.0f, p = 1.0f;
        for (int n = 1; n <= T_STEPS; n++) { p *= a2; s += p; }
        g_csum[idx] = (float)T_STEPS - s;   // sum_k (1 - a2^(200-k))
    }
}

// ---------------- K1: F = ternary(X) @ W1^T + b1  (all timesteps) -----------
#define BM 64
#define BN 64
#define BK 40
__global__ __launch_bounds__(256)
void k_in_gemm(const float* __restrict__ X, const float* __restrict__ thrp,
               const float* __restrict__ W1, const float* __restrict__ b1) {
    __shared__ float As[BK][BM+4];
    __shared__ float Bs[BK][BN+4];
    const int m0 = blockIdx.y * BM;
    const int n0 = blockIdx.x * BN;
    const int tid = threadIdx.x;
    const int tx = tid & 15, ty = tid >> 4;
    const float thr = *thrp;
    float acc[4][4] = {};

    for (int kc = 0; kc < 3; kc++) {       // K=120 = 3 channels * 40 feats
        for (int i = tid; i < BM*BK; i += 256) {
            int mi = i / BK, kk = i % BK;
            int m = m0 + mi;
            int t = m >> 7, b = m & 127;
            float xv = X[((b*3 + kc)*T_STEPS + t)*40 + kk];
            As[kk][mi] = (xv > thr) ? 1.0f : ((xv < -thr) ? -1.0f : 0.0f);
        }
        for (int i = tid; i < BN*BK; i += 256) {
            int ni = i / BK, kk = i % BK;
            Bs[kk][ni] = W1[(n0 + ni)*K_IN + kc*BK + kk];
        }
        __syncthreads();
        #pragma unroll
        for (int kk = 0; kk < BK; kk++) {
            float4 a4 = *(const float4*)&As[kk][ty*4];
            float4 b4 = *(const float4*)&Bs[kk][tx*4];
            float av[4] = {a4.x, a4.y, a4.z, a4.w};
            float bv[4] = {b4.x, b4.y, b4.z, b4.w};
            #pragma unroll
            for (int i = 0; i < 4; i++)
                #pragma unroll
                for (int j = 0; j < 4; j++)
                    acc[i][j] = fmaf(av[i], bv[j], acc[i][j]);
        }
        __syncthreads();
    }
    float4 bias = *(const float4*)&b1[n0 + tx*4];
    float bv[4] = {bias.x, bias.y, bias.z, bias.w};
    #pragma unroll
    for (int i = 0; i < 4; i++) {
        int row = m0 + ty*4 + i;
        float4 outv = make_float4(acc[i][0]+bv[0], acc[i][1]+bv[1],
                                  acc[i][2]+bv[2], acc[i][3]+bv[3]);
        *(float4*)&g_F[(size_t)row*HID + n0 + tx*4] = outv;
    }
}

// ---------------- K2: layer-1 adaptive LIF scan (elementwise over b,h) ------
__global__ __launch_bounds__(256)
void k_l1_scan(const float* __restrict__ tau_m1, const float* __restrict__ tau_adp1) {
    int idx = blockIdx.x * 256 + threadIdx.x;   // idx = b*1024 + h
    int h = idx & (HID-1);
    float alpha = expf(-1.0f / tau_m1[h]);
    float ro    = expf(-1.0f / tau_adp1[h]);
    float mem = 0.0f, spk = 0.0f, bb = 0.01f;
    for (int t = 0; t < T_STEPS; t++) {
        float x = g_F[(size_t)t*BH + idx];
        bb = ro*bb + (1.0f - ro)*spk;
        float Bv = 0.01f + 1.8f*bb;
        mem = alpha*mem + (1.0f - alpha)*x - Bv*spk;
        spk = (mem - Bv > 0.0f) ? 1.0f : 0.0f;
        g_s1[(size_t)t*BH + idx] = (unsigned char)spk;
    }
}

// ---------------- K3: one recurrent timestep (gather + LIF + readout) -------
__global__ __launch_bounds__(256)
void k_step(int t) {
    __shared__ unsigned char s1row[HID];
    __shared__ unsigned char srrow[HID];
    __shared__ float red[256][NOUT];
    const int b = blockIdx.x, tid = threadIdx.x;
    const int p = t & 1;                   // sr_{t-1} lives in parity p

    ((uchar4*)s1row)[tid] = ((const uchar4*)(g_s1 + (size_t)t*BH + b*HID))[tid];
    ((uchar4*)srrow)[tid] = ((const uchar4*)(g_sr + (size_t)p*BH + b*HID))[tid];
    __syncthreads();

    const int j0 = tid * 4;
    float4 acc;
    {
        float4 vb = *(const float4*)&g_biasr[j0];
        acc = make_float4(vb.x, vb.y, vb.z, vb.w);
    }

    // gather: xr += sum_{h: s1=1} WdT[h,:] + sum_{h: sr=1} WrT[h,:]
    #pragma unroll 4
    for (int hw = 0; hw < HID/4; hw++) {
        unsigned d32 = ((const unsigned*)s1row)[hw];
        unsigned r32 = ((const unsigned*)srrow)[hw];
        if ((d32 | r32) == 0u) continue;
        int hb = hw * 4;
        #pragma unroll
        for (int i = 0; i < 4; i++) {
            int h = hb + i;
            if ((d32 >> (8*i)) & 0xffu) {
                float4 w = *(const float4*)&g_WdT[(size_t)h*HID + j0];
                acc.x += w.x; acc.y += w.y; acc.z += w.z; acc.w += w.w;
            }
            if ((r32 >> (8*i)) & 0xffu) {
                float4 w = *(const float4*)&g_WrT[(size_t)h*HID + j0];
                acc.x += w.x; acc.y += w.y; acc.z += w.z; acc.w += w.w;
            }
        }
    }

    // adaptive LIF update for the 4 owned neurons
    const int base = b*HID + j0;
    float4 memv = *(const float4*)&g_memr[base];
    float4 bbv  = *(const float4*)&g_bbr[base];
    float4 alv  = *(const float4*)&g_alphar[j0];
    float4 rov  = *(const float4*)&g_ror[j0];
    float accv[4] = {acc.x, acc.y, acc.z, acc.w};
    float mv[4]   = {memv.x, memv.y, memv.z, memv.w};
    float bbav[4] = {bbv.x, bbv.y, bbv.z, bbv.w};
    float alp[4]  = {alv.x, alv.y, alv.z, alv.w};
    float rop[4]  = {rov.x, rov.y, rov.z, rov.w};
    unsigned char news[4];
    #pragma unroll
    for (int i = 0; i < 4; i++) {
        float spk = (float)srrow[j0 + i];
        float bn = rop[i]*bbav[i] + (1.0f - rop[i])*spk;
        float Bv = 0.01f + 1.8f*bn;
        float mn = alp[i]*mv[i] + (1.0f - alp[i])*accv[i] - Bv*spk;
        news[i] = (mn - Bv > 0.0f) ? 1 : 0;
        mv[i] = mn; bbav[i] = bn;
    }
    *(float4*)&g_memr[base] = make_float4(mv[0], mv[1], mv[2], mv[3]);
    *(float4*)&g_bbr[base]  = make_float4(bbav[0], bbav[1], bbav[2], bbav[3]);
    ((uchar4*)(g_sr + (size_t)(1 - p)*BH + b*HID))[tid] =
        make_uchar4(news[0], news[1], news[2], news[3]);

    // readout of previous step's spikes: y_{t-1}[b,o] = sum_h sr[h] * W2[o,h]
    float part[NOUT] = {};
    for (int h = tid; h < HID; h += 256) {
        if (srrow[h]) {
            const float* w = &g_W2T[h*NOUT];
            #pragma unroll
            for (int o = 0; o < NOUT; o++) part[o] += w[o];
        }
    }
    #pragma unroll
    for (int o = 0; o < NOUT; o++) red[tid][o] = part[o];
    __syncthreads();
    for (int s = 128; s > 0; s >>= 1) {
        if (tid < s)
            #pragma unroll
            for (int o = 0; o < NOUT; o++) red[tid][o] += red[tid + s][o];
        __syncthreads();
    }
    if (t > 0 && tid < NOUT)
        g_racc[b*NOUT + tid] += g_ctab[(t-1)*NOUT + tid] * red[0][tid];
}

// ---------------- K4: final readout (sr_199) + bias + log_softmax -----------
__global__ __launch_bounds__(256)
void k_final(const float* __restrict__ b2, float* __restrict__ out) {
    __shared__ unsigned char srrow[HID];
    __shared__ float red[256][NOUT];
    __shared__ float vals[NOUT];
    __shared__ float lsum;
    const int b = blockIdx.x, tid = threadIdx.x;

    // after step t=199 (p=1), new spikes were written to parity 0
    ((uchar4*)srrow)[tid] = ((const uchar4*)(g_sr + 0 + b*HID))[tid];
    __syncthreads();

    float part[NOUT] = {};
    for (int h = tid; h < HID; h += 256) {
        if (srrow[h]) {
            const float* w = &g_W2T[h*NOUT];
            #pragma unroll
            for (int o = 0; o < NOUT; o++) part[o] += w[o];
        }
    }
    #pragma unroll
    for (int o = 0; o < NOUT; o++) red[tid][o] = part[o];
    __syncthreads();
    for (int s = 128; s > 0; s >>= 1) {
        if (tid < s)
            #pragma unroll
            for (int o = 0; o < NOUT; o++) red[tid][o] += red[tid + s][o];
        __syncthreads();
    }
    if (tid < NOUT) {
        float v = g_racc[b*NOUT + tid]
                + g_ctab[(T_STEPS-1)*NOUT + tid] * red[0][tid]
                + g_csum[tid] * b2[tid];
        vals[tid] = v / (float)T_STEPS;
    }
    __syncthreads();
    if (tid == 0) {
        float m = vals[0];
        for (int o = 1; o < NOUT; o++) m = fmaxf(m, vals[o]);
        float s = 0.0f;
        for (int o = 0; o < NOUT; o++) s += expf(vals[o] - m);
        lsum = m + logf(s);
    }
    __syncthreads();
    if (tid < NOUT) out[b*NOUT + tid] = vals[tid] - lsum;
}

// ---------------- launch -----------------------------------------------------
extern "C" void kernel_launch(void* const* d_in, const int* in_sizes, int n_in,
                              void* d_out, int out_size) {
    const float* X        = (const float*)d_in[0];
    const float* thr      = (const float*)d_in[1];
    const float* W1       = (const float*)d_in[2];
    const float* b1       = (const float*)d_in[3];
    const float* Wd       = (const float*)d_in[4];
    const float* bd       = (const float*)d_in[5];
    const float* Wr       = (const float*)d_in[6];
    const float* br       = (const float*)d_in[7];
    const float* W2       = (const float*)d_in[8];
    const float* b2       = (const float*)d_in[9];
    const float* tau_m1   = (const float*)d_in[10];
    const float* tau_adp1 = (const float*)d_in[11];
    const float* tau_m_r  = (const float*)d_in[12];
    const float* tau_adp_r= (const float*)d_in[13];
    const float* tau_m2   = (const float*)d_in[14];
    float* out = (float*)d_out;

    k_prep_transpose<<<(HID*HID + 255)/256, 256>>>(Wd, Wr, W2);
    k_prep_state<<<(BH + 255)/256, 256>>>(tau_m2, tau_m_r, tau_adp_r, bd, br);
    k_in_gemm<<<dim3(HID/BN, NROWS/BM), 256>>>(X, thr, W1, b1);
    k_l1_scan<<<BH/256, 256>>>(tau_m1, tau_adp1);
    for (int t = 0; t < T_STEPS; t++)
        k_step<<<BATCH, 256>>>(t);
    k_final<<<BATCH, 256>>>(b2, out);
}

// round 2
// speedup vs baseline: 1.0029x; 1.0029x over previous
#include <cuda_runtime.h>
#include <math.h>

#define T_STEPS 200
#define BATCH   128
#define HID     1024
#define K_IN    120
#define NOUT    12
#define BH      (BATCH*HID)      // 131072
#define NROWS   (T_STEPS*BATCH)  // 25600

// ---------------- static device scratch (no allocations allowed) ------------
__device__ float         g_F[NROWS*HID];       // layer-1 drive, all timesteps (105 MB)
__device__ unsigned char g_s1[NROWS*HID];      // layer-1 spikes, all timesteps (26 MB)
__device__ unsigned char g_sr[2*BH];           // recurrent spikes, ping-pong
__device__ float         g_memr[BH];
__device__ float         g_bbr[BH];
__device__ float         g_racc[BATCH*NOUT];
__device__ float         g_WdT[HID*HID];       // Wd transposed: [h][j]
__device__ float         g_WrT[HID*HID];       // Wr transposed: [h][j]
__device__ float         g_W2T[HID*NOUT];      // W2 transposed: [h][o]
__device__ float         g_ctab[T_STEPS*NOUT]; // c_k[o] = 1 - alpha2^(200-k)
__device__ float         g_csum[NOUT];         // sum_k c_k[o]
__device__ float         g_alphar[HID];        // exp(-1/tau_m_r)
__device__ float         g_ror[HID];           // exp(-1/tau_adp_r)
__device__ float         g_biasr[HID];         // bd + br

// ---------------- prep: transposes ------------------------------------------
__global__ void k_prep_transpose(const float* __restrict__ Wd,
                                 const float* __restrict__ Wr,
                                 const float* __restrict__ W2) {
    int idx = blockIdx.x * blockDim.x + threadIdx.x;
    if (idx < HID*HID) {
        int h = idx / HID, j = idx % HID;
        g_WdT[idx] = Wd[j*HID + h];
        g_WrT[idx] = Wr[j*HID + h];
    }
    if (idx < HID*NOUT) {
        int h = idx / NOUT, o = idx % NOUT;
        g_W2T[idx] = W2[o*HID + h];
    }
}

// ---------------- prep: state init + coefficient tables ---------------------
__global__ void k_prep_state(const float* __restrict__ tau_m2,
                             const float* __restrict__ tau_m_r,
                             const float* __restrict__ tau_adp_r,
                             const float* __restrict__ bd,
                             const float* __restrict__ br) {
    int idx = blockIdx.x * blockDim.x + threadIdx.x;
    if (idx < BH) {
        g_memr[idx] = 0.0f;
        g_bbr[idx]  = 0.01f;
        g_sr[idx]        = 0;
        g_sr[BH + idx]   = 0;
    }
    if (idx < HID) {
        g_alphar[idx] = expf(-1.0f / tau_m_r[idx]);
        g_ror[idx]    = expf(-1.0f / tau_adp_r[idx]);
        g_biasr[idx]  = bd[idx] + br[idx];
    }
    if (idx < BATCH*NOUT) g_racc[idx] = 0.0f;
    if (idx < T_STEPS*NOUT) {
        int k = idx / NOUT, o = idx % NOUT;
        float a2 = expf(-1.0f / tau_m2[o]);
        g_ctab[idx] = 1.0f - powf(a2, (float)(T_STEPS - k));
    }
    if (idx < NOUT) {
        float a2 = expf(-1.0f / tau_m2[idx]);
        float s = 0.0f, p = 1.0f;
        for (int n = 1; n <= T_STEPS; n++) { p *= a2; s += p; }
        g_csum[idx] = (float)T_STEPS - s;   // sum_k (1 - a2^(200-k))
    }
}

// ---------------- K1: F = ternary(X) @ W1^T + b1  (all timesteps) -----------
#define BM 64
#define BN 64
#define BK 40
__global__ __launch_bounds__(256)
void k_in_gemm(const float* __restrict__ X, const float* __restrict__ thrp,
               const float* __restrict__ W1, const float* __restrict__ b1) {
    __shared__ float As[BK][BM+4];
    __shared__ float Bs[BK][BN+4];
    const int m0 = blockIdx.y * BM;
    const int n0 = blockIdx.x * BN;
    const int tid = threadIdx.x;
    const int tx = tid & 15, ty = tid >> 4;
    const float thr = *thrp;
    float acc[4][4] = {};

    for (int kc = 0; kc < 3; kc++) {       // K=120 = 3 channels * 40 feats
        for (int i = tid; i < BM*BK; i += 256) {
            int mi = i / BK, kk = i % BK;
            int m = m0 + mi;
            int t = m >> 7, b = m & 127;
            float xv = X[((b*3 + kc)*T_STEPS + t)*40 + kk];
            As[kk][mi] = (xv > thr) ? 1.0f : ((xv < -thr) ? -1.0f : 0.0f);
        }
        for (int i = tid; i < BN*BK; i += 256) {
            int ni = i / BK, kk = i % BK;
            Bs[kk][ni] = W1[(n0 + ni)*K_IN + kc*BK + kk];
        }
        __syncthreads();
        #pragma unroll
        for (int kk = 0; kk < BK; kk++) {
            float4 a4 = *(const float4*)&As[kk][ty*4];
            float4 b4 = *(const float4*)&Bs[kk][tx*4];
            float av[4] = {a4.x, a4.y, a4.z, a4.w};
            float bv[4] = {b4.x, b4.y, b4.z, b4.w};
            #pragma unroll
            for (int i = 0; i < 4; i++)
                #pragma unroll
                for (int j = 0; j < 4; j++)
                    acc[i][j] = fmaf(av[i], bv[j], acc[i][j]);
        }
        __syncthreads();
    }
    float4 bias = *(const float4*)&b1[n0 + tx*4];
    float bv[4] = {bias.x, bias.y, bias.z, bias.w};
    #pragma unroll
    for (int i = 0; i < 4; i++) {
        int row = m0 + ty*4 + i;
        float4 outv = make_float4(acc[i][0]+bv[0], acc[i][1]+bv[1],
                                  acc[i][2]+bv[2], acc[i][3]+bv[3]);
        *(float4*)&g_F[(size_t)row*HID + n0 + tx*4] = outv;
    }
}

// ---------------- K2: layer-1 adaptive LIF scan (elementwise over b,h) ------
__global__ __launch_bounds__(256)
void k_l1_scan(const float* __restrict__ tau_m1, const float* __restrict__ tau_adp1) {
    int idx = blockIdx.x * 256 + threadIdx.x;   // idx = b*1024 + h
    int h = idx & (HID-1);
    float alpha = expf(-1.0f / tau_m1[h]);
    float ro    = expf(-1.0f / tau_adp1[h]);
    float mem = 0.0f, spk = 0.0f, bb = 0.01f;
    for (int t = 0; t < T_STEPS; t++) {
        float x = g_F[(size_t)t*BH + idx];
        bb = ro*bb + (1.0f - ro)*spk;
        float Bv = 0.01f + 1.8f*bb;
        mem = alpha*mem + (1.0f - alpha)*x - Bv*spk;
        spk = (mem - Bv > 0.0f) ? 1.0f : 0.0f;
        g_s1[(size_t)t*BH + idx] = (unsigned char)spk;
    }
}

// ---------------- K3: one recurrent timestep (gather + LIF + readout) -------
__global__ __launch_bounds__(256)
void k_step(int t) {
    __shared__ unsigned char s1row[HID];
    __shared__ unsigned char srrow[HID];
    __shared__ float red[256][NOUT];
    const int b = blockIdx.x, tid = threadIdx.x;
    const int p = t & 1;                   // sr_{t-1} lives in parity p

    ((uchar4*)s1row)[tid] = ((const uchar4*)(g_s1 + (size_t)t*BH + b*HID))[tid];
    ((uchar4*)srrow)[tid] = ((const uchar4*)(g_sr + (size_t)p*BH + b*HID))[tid];
    __syncthreads();

    const int j0 = tid * 4;
    float4 acc;
    {
        float4 vb = *(const float4*)&g_biasr[j0];
        acc = make_float4(vb.x, vb.y, vb.z, vb.w);
    }

    // gather: xr += sum_{h: s1=1} WdT[h,:] + sum_{h: sr=1} WrT[h,:]
    #pragma unroll 4
    for (int hw = 0; hw < HID/4; hw++) {
        unsigned d32 = ((const unsigned*)s1row)[hw];
        unsigned r32 = ((const unsigned*)srrow)[hw];
        if ((d32 | r32) == 0u) continue;
        int hb = hw * 4;
        #pragma unroll
        for (int i = 0; i < 4; i++) {
            int h = hb + i;
            if ((d32 >> (8*i)) & 0xffu) {
                float4 w = *(const float4*)&g_WdT[(size_t)h*HID + j0];
                acc.x += w.x; acc.y += w.y; acc.z += w.z; acc.w += w.w;
            }
            if ((r32 >> (8*i)) & 0xffu) {
                float4 w = *(const float4*)&g_WrT[(size_t)h*HID + j0];
                acc.x += w.x; acc.y += w.y; acc.z += w.z; acc.w += w.w;
            }
        }
    }

    // adaptive LIF update for the 4 owned neurons
    const int base = b*HID + j0;
    float4 memv = *(const float4*)&g_memr[base];
    float4 bbv  = *(const float4*)&g_bbr[base];
    float4 alv  = *(const float4*)&g_alphar[j0];
    float4 rov  = *(const float4*)&g_ror[j0];
    float accv[4] = {acc.x, acc.y, acc.z, acc.w};
    float mv[4]   = {memv.x, memv.y, memv.z, memv.w};
    float bbav[4] = {bbv.x, bbv.y, bbv.z, bbv.w};
    float alp[4]  = {alv.x, alv.y, alv.z, alv.w};
    float rop[4]  = {rov.x, rov.y, rov.z, rov.w};
    unsigned char news[4];
    #pragma unroll
    for (int i = 0; i < 4; i++) {
        float spk = (float)srrow[j0 + i];
        float bn = rop[i]*bbav[i] + (1.0f - rop[i])*spk;
        float Bv = 0.01f + 1.8f*bn;
        float mn = alp[i]*mv[i] + (1.0f - alp[i])*accv[i] - Bv*spk;
        news[i] = (mn - Bv > 0.0f) ? 1 : 0;
        mv[i] = mn; bbav[i] = bn;
    }
    *(float4*)&g_memr[base] = make_float4(mv[0], mv[1], mv[2], mv[3]);
    *(float4*)&g_bbr[base]  = make_float4(bbav[0], bbav[1], bbav[2], bbav[3]);
    ((uchar4*)(g_sr + (size_t)(1 - p)*BH + b*HID))[tid] =
        make_uchar4(news[0], news[1], news[2], news[3]);

    // readout of previous step's spikes: y_{t-1}[b,o] = sum_h sr[h] * W2[o,h]
    float part[NOUT] = {};
    for (int h = tid; h < HID; h += 256) {
        if (srrow[h]) {
            const float* w = &g_W2T[h*NOUT];
            #pragma unroll
            for (int o = 0; o < NOUT; o++) part[o] += w[o];
        }
    }
    #pragma unroll
    for (int o = 0; o < NOUT; o++) red[tid][o] = part[o];
    __syncthreads();
    for (int s = 128; s > 0; s >>= 1) {
        if (tid < s)
            #pragma unroll
            for (int o = 0; o < NOUT; o++) red[tid][o] += red[tid + s][o];
        __syncthreads();
    }
    if (t > 0 && tid < NOUT)
        g_racc[b*NOUT + tid] += g_ctab[(t-1)*NOUT + tid] * red[0][tid];
}

// ---------------- K4: final readout (sr_199) + bias + log_softmax -----------
__global__ __launch_bounds__(256)
void k_final(const float* __restrict__ b2, float* __restrict__ out) {
    __shared__ unsigned char srrow[HID];
    __shared__ float red[256][NOUT];
    __shared__ float vals[NOUT];
    __shared__ float lsum;
    const int b = blockIdx.x, tid = threadIdx.x;

    // after step t=199 (p=1), new spikes were written to parity 0
    ((uchar4*)srrow)[tid] = ((const uchar4*)(g_sr + 0 + b*HID))[tid];
    __syncthreads();

    float part[NOUT] = {};
    for (int h = tid; h < HID; h += 256) {
        if (srrow[h]) {
            const float* w = &g_W2T[h*NOUT];
            #pragma unroll
            for (int o = 0; o < NOUT; o++) part[o] += w[o];
        }
    }
    #pragma unroll
    for (int o = 0; o < NOUT; o++) red[tid][o] = part[o];
    __syncthreads();
    for (int s = 128; s > 0; s >>= 1) {
        if (tid < s)
            #pragma unroll
            for (int o = 0; o < NOUT; o++) red[tid][o] += red[tid + s][o];
        __syncthreads();
    }
    if (tid < NOUT) {
        float v = g_racc[b*NOUT + tid]
                + g_ctab[(T_STEPS-1)*NOUT + tid] * red[0][tid]
                + g_csum[tid] * b2[tid];
        vals[tid] = v / (float)T_STEPS;
    }
    __syncthreads();
    if (tid == 0) {
        float m = vals[0];
        for (int o = 1; o < NOUT; o++) m = fmaxf(m, vals[o]);
        float s = 0.0f;
        for (int o = 0; o < NOUT; o++) s += expf(vals[o] - m);
        lsum = m + logf(s);
    }
    __syncthreads();
    if (tid < NOUT) out[b*NOUT + tid] = vals[tid] - lsum;
}

// ---------------- launch -----------------------------------------------------
extern "C" void kernel_launch(void* const* d_in, const int* in_sizes, int n_in,
                              void* d_out, int out_size) {
    const float* X        = (const float*)d_in[0];
    const float* thr      = (const float*)d_in[1];
    const float* W1       = (const float*)d_in[2];
    const float* b1       = (const float*)d_in[3];
    const float* Wd       = (const float*)d_in[4];
    const float* bd       = (const float*)d_in[5];
    const float* Wr       = (const float*)d_in[6];
    const float* br       = (const float*)d_in[7];
    const float* W2       = (const float*)d_in[8];
    const float* b2       = (const float*)d_in[9];
    const float* tau_m1   = (const float*)d_in[10];
    const float* tau_adp1 = (const float*)d_in[11];
    const float* tau_m_r  = (const float*)d_in[12];
    const float* tau_adp_r= (const float*)d_in[13];
    const float* tau_m2   = (const float*)d_in[14];
    float* out = (float*)d_out;

    k_prep_transpose<<<(HID*HID + 255)/256, 256>>>(Wd, Wr, W2);
    k_prep_state<<<(BH + 255)/256, 256>>>(tau_m2, tau_m_r, tau_adp_r, bd, br);
    k_in_gemm<<<dim3(HID/BN, NROWS/BM), 256>>>(X, thr, W1, b1);
    k_l1_scan<<<BH/256, 256>>>(tau_m1, tau_adp1);
    for (int t = 0; t < T_STEPS; t++)
        k_step<<<BATCH, 256>>>(t);
    k_final<<<BATCH, 256>>>(b2, out);
}

// round 5
// speedup vs baseline: 3.5706x; 3.5603x over previous
#include <cuda_runtime.h>
#include <cuda_bf16.h>
#include <math.h>

#define T_STEPS 200
#define BATCH   128
#define HID     1024
#define K_IN    120
#define NOUT    12
#define BH      (BATCH*HID)      // 131072
#define NROWS   (T_STEPS*BATCH)  // 25600

// ---------------- static device scratch (no allocations allowed) ------------
__device__ float          g_F[NROWS*HID];       // W1 drive, then overwritten by D = S1@Wd^T
__device__ float          g_WrT[1025*HID];      // Wr^T fp32 [h][j] + zero pad row
__device__ __nv_bfloat16  g_WdB[3][HID*HID];    // Wd 3-way bf16 split, [j][h] native layout
__device__ float          g_W2T[HID*NOUT];
__device__ unsigned       g_m1[(size_t)BATCH*T_STEPS*32];    // layer-1 spike masks (h-linear)
__device__ unsigned       g_masks[(size_t)BATCH*T_STEPS*32]; // recurrent spike ballots
__device__ float          g_ctab[T_STEPS*NOUT];
__device__ float          g_csum[NOUT];

// ---------------- prep: Wr transpose, Wd 3-split, W2T, tables ----------------
__global__ __launch_bounds__(256)
void k_prep(const float* __restrict__ Wd, const float* __restrict__ Wr,
            const float* __restrict__ W2, const float* __restrict__ tau_m2) {
    int idx = blockIdx.x * 256 + threadIdx.x;
    if (idx < HID*HID) {
        int j = idx >> 10, h = idx & 1023;
        g_WrT[(size_t)h*HID + j] = Wr[idx];      // Wr^T[h][j]
        float w = Wd[idx];
        __nv_bfloat16 h1 = __float2bfloat16(w);
        float r1 = w - __bfloat162float(h1);
        __nv_bfloat16 h2 = __float2bfloat16(r1);
        float r2 = r1 - __bfloat162float(h2);
        __nv_bfloat16 h3 = __float2bfloat16(r2);
        g_WdB[0][idx] = h1;
        g_WdB[1][idx] = h2;
        g_WdB[2][idx] = h3;
    }
    if (idx < HID*NOUT) {
        int h = idx / NOUT, o = idx % NOUT;
        g_W2T[idx] = W2[o*HID + h];
    }
    if (idx < T_STEPS*NOUT) {
        int k = idx / NOUT, o = idx % NOUT;
        float a2 = expf(-1.0f / tau_m2[o]);
        g_ctab[idx] = 1.0f - powf(a2, (float)(T_STEPS - k));
    }
    if (idx < NOUT) {
        float a2 = expf(-1.0f / tau_m2[idx]);
        float s = 0.0f, p = 1.0f;
        for (int n = 1; n <= T_STEPS; n++) { p *= a2; s += p; }
        g_csum[idx] = (float)T_STEPS - s;
    }
    if (idx < HID) g_WrT[(size_t)1024*HID + idx] = 0.0f;   // zero pad row
}

// ---------------- K1: F = ternary(X) @ W1^T + b1 ------------------------------
#define BM 64
#define BN 64
#define BK 40
__global__ __launch_bounds__(256)
void k_in_gemm(const float* __restrict__ X, const float* __restrict__ thrp,
               const float* __restrict__ W1, const float* __restrict__ b1) {
    __shared__ float As[BK][BM+4];
    __shared__ float Bs[BK][BN+4];
    const int m0 = blockIdx.y * BM;
    const int n0 = blockIdx.x * BN;
    const int tid = threadIdx.x;
    const int tx = tid & 15, ty = tid >> 4;
    const float thr = *thrp;
    float acc[4][4] = {};
    for (int kc = 0; kc < 3; kc++) {
        for (int i = tid; i < BM*BK; i += 256) {
            int mi = i / BK, kk = i % BK;
            int m = m0 + mi;
            int t = m >> 7, b = m & 127;
            float xv = X[((b*3 + kc)*T_STEPS + t)*40 + kk];
            As[kk][mi] = (xv > thr) ? 1.0f : ((xv < -thr) ? -1.0f : 0.0f);
        }
        for (int i = tid; i < BN*BK; i += 256) {
            int ni = i / BK, kk = i % BK;
            Bs[kk][ni] = W1[(n0 + ni)*K_IN + kc*BK + kk];
        }
        __syncthreads();
        #pragma unroll
        for (int kk = 0; kk < BK; kk++) {
            float4 a4 = *(const float4*)&As[kk][ty*4];
            float4 b4 = *(const float4*)&Bs[kk][tx*4];
            float av[4] = {a4.x, a4.y, a4.z, a4.w};
            float bv[4] = {b4.x, b4.y, b4.z, b4.w};
            #pragma unroll
            for (int i = 0; i < 4; i++)
                #pragma unroll
                for (int j = 0; j < 4; j++)
                    acc[i][j] = fmaf(av[i], bv[j], acc[i][j]);
        }
        __syncthreads();
    }
    float4 bias = *(const float4*)&b1[n0 + tx*4];
    float bv[4] = {bias.x, bias.y, bias.z, bias.w};
    #pragma unroll
    for (int i = 0; i < 4; i++) {
        int row = m0 + ty*4 + i;
        float4 outv = make_float4(acc[i][0]+bv[0], acc[i][1]+bv[1],
                                  acc[i][2]+bv[2], acc[i][3]+bv[3]);
        *(float4*)&g_F[(size_t)row*HID + n0 + tx*4] = outv;
    }
}

// ---------------- K2: layer-1 LIF scan -> h-linear spike bitmasks -------------
__global__ __launch_bounds__(256)
void k_l1_scan(const float* __restrict__ tau_m1, const float* __restrict__ tau_adp1) {
    int idx = blockIdx.x * 256 + threadIdx.x;    // b*1024 + h
    int h = idx & 1023, b = idx >> 10;
    float alpha = expf(-1.0f / tau_m1[h]);
    float ro    = expf(-1.0f / tau_adp1[h]);
    float mem = 0.0f, spk = 0.0f, bb = 0.01f;
    int word = (h >> 5) & 31;
    int lane = threadIdx.x & 31;
    #pragma unroll 4
    for (int t = 0; t < T_STEPS; t++) {
        float x = g_F[(size_t)t*BH + idx];
        bb = ro*bb + (1.0f - ro)*spk;
        float Bv = 0.01f + 1.8f*bb;
        mem = alpha*mem + (1.0f - alpha)*x - Bv*spk;
        spk = (mem - Bv > 0.0f) ? 1.0f : 0.0f;
        unsigned m = __ballot_sync(0xffffffffu, spk != 0.0f);
        if (lane == 0) g_m1[((size_t)b*T_STEPS + t)*32 + word] = m;
    }
}

// ---------------- K3: D = S1 @ Wd^T via mma.sync bf16 3-split -----------------
// grid (16 n-tiles, 200 m-tiles of 128), 256 threads (8 warps: 4 m-warps x 2 n-warps)
__device__ __forceinline__ void mma16816(float* c, const unsigned* a, unsigned b0, unsigned b1) {
    asm volatile("mma.sync.aligned.m16n8k16.row.col.f32.bf16.bf16.f32 "
        "{%0,%1,%2,%3}, {%4,%5,%6,%7}, {%8,%9}, {%0,%1,%2,%3};"
        : "+f"(c[0]), "+f"(c[1]), "+f"(c[2]), "+f"(c[3])
        : "r"(a[0]), "r"(a[1]), "r"(a[2]), "r"(a[3]), "r"(b0), "r"(b1));
}
__device__ __forceinline__ unsigned spike_pack(unsigned m, int c) {
    return (((m >> c) & 1u) ? 0x3F80u : 0u) | (((m >> (c+1)) & 1u) ? 0x3F800000u : 0u);
}
__global__ __launch_bounds__(256)
void k_dgemm() {
    __shared__ unsigned Bs[3][64][17];   // [split][n][k-pair], BK=32
    const int tid = threadIdx.x, lane = tid & 31, w = tid >> 5;
    const int wm = w & 3, wn = w >> 2;
    const int Mb = blockIdx.y * 128, Nb = blockIdx.x * 64;
    float acc[2][4][4] = {};             // [m-frag][n-frag][reg]

    // mask row pointers for this lane's 4 rows (wm*32 + lane/4 + {0,8,16,24})
    const unsigned* mp[4];
    #pragma unroll
    for (int q = 0; q < 4; q++) {
        int m = Mb + wm*32 + (lane >> 2) + q*8;
        int b = m & 127, t = m >> 7;
        mp[q] = g_m1 + ((size_t)b*T_STEPS + t)*32;
    }
    const unsigned* wdb = (const unsigned*)g_WdB;   // 3 splits contiguous, u32 view

    for (int kc = 0; kc < 32; kc++) {
        #pragma unroll
        for (int e = tid; e < 3072; e += 256) {
            int s = e >> 10, rem = e & 1023, n = rem >> 4, kp = rem & 15;
            Bs[s][n][kp] = wdb[(size_t)s*524288 + (size_t)(Nb + n)*512 + kc*16 + kp];
        }
        __syncthreads();
        unsigned mk[4];
        #pragma unroll
        for (int q = 0; q < 4; q++) mk[q] = mp[q][kc];
        #pragma unroll
        for (int e = 0; e < 2; e++) {            // two k16 halves of the 32-chunk
            int cb = e*16 + (lane & 3)*2;
            unsigned a[2][4];
            #pragma unroll
            for (int mf = 0; mf < 2; mf++) {
                a[mf][0] = spike_pack(mk[mf*2 + 0], cb);
                a[mf][1] = spike_pack(mk[mf*2 + 1], cb);
                a[mf][2] = spike_pack(mk[mf*2 + 0], cb + 8);
                a[mf][3] = spike_pack(mk[mf*2 + 1], cb + 8);
            }
            #pragma unroll
            for (int s = 0; s < 3; s++)
                #pragma unroll
                for (int nf = 0; nf < 4; nf++) {
                    int n = wn*32 + nf*8 + (lane >> 2);
                    int kp = e*8 + (lane & 3);
                    unsigned b0 = Bs[s][n][kp];
                    unsigned b1 = Bs[s][n][kp + 4];
                    mma16816(acc[0][nf], a[0], b0, b1);
                    mma16816(acc[1][nf], a[1], b0, b1);
                }
        }
        __syncthreads();
    }
    // epilogue: D rows (t*128+b) match g_F layout
    #pragma unroll
    for (int mf = 0; mf < 2; mf++)
        #pragma unroll
        for (int nf = 0; nf < 4; nf++) {
            int col = Nb + wn*32 + nf*8 + (lane & 3)*2;
            int row = Mb + wm*32 + mf*16 + (lane >> 2);
            *(float2*)&g_F[(size_t)row*HID + col] =
                make_float2(acc[mf][nf][0], acc[mf][nf][1]);
            *(float2*)&g_F[(size_t)(row + 8)*HID + col] =
                make_float2(acc[mf][nf][2], acc[mf][nf][3]);
        }
}

// ---------------- K4: persistent recurrent loop (1 block per batch) -----------
__global__ __launch_bounds__(256)
void k_steps(const float* __restrict__ tau_m_r, const float* __restrict__ tau_adp_r,
             const float* __restrict__ bd, const float* __restrict__ br) {
    __shared__ unsigned s_srm[32];
    __shared__ __align__(16) unsigned short list[1032];
    __shared__ int s_cnt[32];
    __shared__ int s_off[32];
    __shared__ int s_tot, s_n8;
    const int b = blockIdx.x, tid = threadIdx.x;
    const int lane = tid & 31, w = tid >> 5;
    const int j0 = tid * 4;

    float al[4], ro[4], bi[4], mem[4], bb[4], sp[4];
    #pragma unroll
    for (int i = 0; i < 4; i++) {
        al[i] = expf(-1.0f / tau_m_r[j0 + i]);
        ro[i] = expf(-1.0f / tau_adp_r[j0 + i]);
        bi[i] = bd[j0 + i] + br[j0 + i];
        mem[i] = 0.0f; bb[i] = 0.01f; sp[i] = 0.0f;
    }
    if (tid < 32) s_srm[tid] = 0u;
    __syncthreads();

    const float* wp = g_WrT + j0;                       // float4 slice per thread
    const float* fbase = g_F + (size_t)b*HID + j0;
    unsigned* mout = g_masks + (size_t)b*T_STEPS*32;

    for (int t = 0; t < T_STEPS; t++) {
        // 1. counts of active sr words
        unsigned myw = (tid < 32) ? s_srm[tid] : 0u;
        if (tid < 32) s_cnt[tid] = __popc(myw);
        __syncthreads();
        // 2. exclusive scan (warp 0)
        if (tid < 32) {
            int c = s_cnt[tid];
            int inc = c;
            #pragma unroll
            for (int d = 1; d < 32; d <<= 1) {
                int v = __shfl_up_sync(0xffffffffu, inc, d);
                if (lane >= d) inc += v;
            }
            s_off[tid] = inc - c;
            if (tid == 31) { s_tot = inc; s_n8 = (inc + 7) & ~7; }
        }
        __syncthreads();
        // 3. expand ballots into row list (ballot word v: h = (v>>2)*128 + l*4 + (v&3))
        if (tid < 32) {
            int o = s_off[tid];
            unsigned m = myw;
            int base = (tid >> 2)*128 + (tid & 3);
            while (m) {
                int l = __ffs(m) - 1; m &= m - 1;
                list[o++] = (unsigned short)(base + l*4);
            }
        }
        for (int i = s_tot + tid; i < s_n8; i += 256) list[i] = (unsigned short)1024;
        __syncthreads();
        // 4. fp32 gather over active rows
        const int n8 = s_n8;
        float4 f4 = *(const float4*)(fbase + (size_t)t*BH);
        float a0 = f4.x + bi[0], a1 = f4.y + bi[1], a2 = f4.z + bi[2], a3 = f4.w + bi[3];
        for (int i = 0; i < n8; i += 8) {
            uint4 u = *(const uint4*)&list[i];
            int e0 = u.x & 0xffff, e1 = u.x >> 16;
            int e2 = u.y & 0xffff, e3 = u.y >> 16;
            int e4 = u.z & 0xffff, e5 = u.z >> 16;
            int e6 = u.w & 0xffff, e7 = u.w >> 16;
            float4 v0 = *(const float4*)(wp + (size_t)e0*HID);
            float4 v1 = *(const float4*)(wp + (size_t)e1*HID);
            float4 v2 = *(const float4*)(wp + (size_t)e2*HID);
            float4 v3 = *(const float4*)(wp + (size_t)e3*HID);
            float4 v4 = *(const float4*)(wp + (size_t)e4*HID);
            float4 v5 = *(const float4*)(wp + (size_t)e5*HID);
            float4 v6 = *(const float4*)(wp + (size_t)e6*HID);
            float4 v7 = *(const float4*)(wp + (size_t)e7*HID);
            a0 += ((v0.x + v1.x) + (v2.x + v3.x)) + ((v4.x + v5.x) + (v6.x + v7.x));
            a1 += ((v0.y + v1.y) + (v2.y + v3.y)) + ((v4.y + v5.y) + (v6.y + v7.y));
            a2 += ((v0.z + v1.z) + (v2.z + v3.z)) + ((v4.z + v5.z) + (v6.z + v7.z));
            a3 += ((v0.w + v1.w) + (v2.w + v3.w)) + ((v4.w + v5.w) + (v6.w + v7.w));
        }
        float x[4] = {a0, a1, a2, a3};
        // 5. adaptive LIF update (4 neurons)
        #pragma unroll
        for (int i = 0; i < 4; i++) {
            bb[i] = ro[i]*bb[i] + (1.0f - ro[i])*sp[i];
            float Bv = 0.01f + 1.8f*bb[i];
            mem[i] = al[i]*mem[i] + (1.0f - al[i])*x[i] - Bv*sp[i];
            sp[i] = (mem[i] - Bv > 0.0f) ? 1.0f : 0.0f;
        }
        // 6. ballots -> smem (next step) + global (readout)
        #pragma unroll
        for (int i = 0; i < 4; i++) {
            unsigned m = __ballot_sync(0xffffffffu, sp[i] != 0.0f);
            if (lane == 0) {
                s_srm[w*4 + i] = m;
                mout[t*32 + w*4 + i] = m;
            }
        }
        __syncthreads();
    }
}

// ---------------- K5: readout + log_softmax -----------------------------------
__global__ __launch_bounds__(256)
void k_readout(const float* __restrict__ b2, float* __restrict__ out) {
    __shared__ float red[256][NOUT];
    __shared__ float vals[NOUT];
    __shared__ float s_l;
    const int b = blockIdx.x, tid = threadIdx.x;
    float acc[NOUT] = {};
    if (tid < T_STEPS) {
        float sum[NOUT] = {};
        const unsigned* gm = g_masks + ((size_t)b*T_STEPS + tid)*32;
        for (int v = 0; v < 32; v++) {
            unsigned m = gm[v];
            int base = (v >> 2)*128 + (v & 3);
            while (m) {
                int l = __ffs(m) - 1; m &= m - 1;
                const float* w2 = &g_W2T[(base + l*4)*NOUT];
                #pragma unroll
                for (int o = 0; o < NOUT; o++) sum[o] += w2[o];
            }
        }
        const float* c = &g_ctab[tid*NOUT];
        #pragma unroll
        for (int o = 0; o < NOUT; o++) acc[o] = c[o]*sum[o];
    }
    #pragma unroll
    for (int o = 0; o < NOUT; o++) red[tid][o] = acc[o];
    __syncthreads();
    for (int s = 128; s > 0; s >>= 1) {
        if (tid < s)
            #pragma unroll
            for (int o = 0; o < NOUT; o++) red[tid][o] += red[tid + s][o];
        __syncthreads();
    }
    if (tid < NOUT)
        vals[tid] = (red[0][tid] + g_csum[tid]*b2[tid]) * (1.0f / (float)T_STEPS);
    __syncthreads();
    if (tid == 0) {
        float m = vals[0];
        for (int o = 1; o < NOUT; o++) m = fmaxf(m, vals[o]);
        float s = 0.0f;
        for (int o = 0; o < NOUT; o++) s += expf(vals[o] - m);
        s_l = m + logf(s);
    }
    __syncthreads();
    if (tid < NOUT) out[b*NOUT + tid] = vals[tid] - s_l;
}

// ---------------- launch -------------------------------------------------------
extern "C" void kernel_launch(void* const* d_in, const int* in_sizes, int n_in,
                              void* d_out, int out_size) {
    const float* X        = (const float*)d_in[0];
    const float* thr      = (const float*)d_in[1];
    const float* W1       = (const float*)d_in[2];
    const float* b1       = (const float*)d_in[3];
    const float* Wd       = (const float*)d_in[4];
    const float* bd       = (const float*)d_in[5];
    const float* Wr       = (const float*)d_in[6];
    const float* br       = (const float*)d_in[7];
    const float* W2       = (const float*)d_in[8];
    const float* b2       = (const float*)d_in[9];
    const float* tau_m1   = (const float*)d_in[10];
    const float* tau_adp1 = (const float*)d_in[11];
    const float* tau_m_r  = (const float*)d_in[12];
    const float* tau_adp_r= (const float*)d_in[13];
    const float* tau_m2   = (const float*)d_in[14];
    float* out = (float*)d_out;

    k_prep<<<(HID*HID + 255)/256, 256>>>(Wd, Wr, W2, tau_m2);
    k_in_gemm<<<dim3(HID/BN, NROWS/BM), 256>>>(X, thr, W1, b1);
    k_l1_scan<<<BH/256, 256>>>(tau_m1, tau_adp1);
    k_dgemm<<<dim3(16, 200), 256>>>();
    k_steps<<<BATCH, 256>>>(tau_m_r, tau_adp_r, bd, br);
    k_readout<<<BATCH, 256>>>(b2, out);
}

// round 6
// speedup vs baseline: 3.8030x; 1.0651x over previous
#include <cuda_runtime.h>
#include <cuda_bf16.h>
#include <math.h>

#define T_STEPS 200
#define BATCH   128
#define HID     1024
#define K_IN    120
#define NOUT    12
#define BH      (BATCH*HID)      // 131072
#define NROWS   (T_STEPS*BATCH)  // 25600

// ---------------- static device scratch (no allocations allowed) ------------
__device__ float          g_F[NROWS*HID];       // W1 drive, then overwritten by D = S1@Wd^T
__device__ float          g_WrT[1025*HID];      // Wr^T fp32 [h][j] + zero pad row
__device__ __nv_bfloat16  g_WdB[3][HID*HID];    // Wd 3-way bf16 split, [j][h] native layout
__device__ float          g_W2T[HID*NOUT];
__device__ unsigned       g_m1[(size_t)BATCH*T_STEPS*32];    // layer-1 spike masks (h-linear)
__device__ unsigned       g_masks[(size_t)BATCH*T_STEPS*32]; // recurrent spike ballots
__device__ float          g_ctab[T_STEPS*NOUT];
__device__ float          g_csum[NOUT];

// ---------------- prep: Wr transpose, Wd 3-split, W2T, tables ----------------
__global__ __launch_bounds__(256)
void k_prep(const float* __restrict__ Wd, const float* __restrict__ Wr,
            const float* __restrict__ W2, const float* __restrict__ tau_m2) {
    int idx = blockIdx.x * 256 + threadIdx.x;
    if (idx < HID*HID) {
        int j = idx >> 10, h = idx & 1023;
        g_WrT[(size_t)h*HID + j] = Wr[idx];      // Wr^T[h][j]
        float w = Wd[idx];
        __nv_bfloat16 h1 = __float2bfloat16(w);
        float r1 = w - __bfloat162float(h1);
        __nv_bfloat16 h2 = __float2bfloat16(r1);
        float r2 = r1 - __bfloat162float(h2);
        __nv_bfloat16 h3 = __float2bfloat16(r2);
        g_WdB[0][idx] = h1;
        g_WdB[1][idx] = h2;
        g_WdB[2][idx] = h3;
    }
    if (idx < HID*NOUT) {
        int h = idx / NOUT, o = idx % NOUT;
        g_W2T[idx] = W2[o*HID + h];
    }
    if (idx < T_STEPS*NOUT) {
        int k = idx / NOUT, o = idx % NOUT;
        float a2 = expf(-1.0f / tau_m2[o]);
        g_ctab[idx] = 1.0f - powf(a2, (float)(T_STEPS - k));
    }
    if (idx < NOUT) {
        float a2 = expf(-1.0f / tau_m2[idx]);
        float s = 0.0f, p = 1.0f;
        for (int n = 1; n <= T_STEPS; n++) { p *= a2; s += p; }
        g_csum[idx] = (float)T_STEPS - s;
    }
    if (idx < HID) g_WrT[(size_t)1024*HID + idx] = 0.0f;   // zero pad row
}

// ---------------- K1: F = ternary(X) @ W1^T + b1 ------------------------------
#define BM 64
#define BN 64
#define BK 40
__global__ __launch_bounds__(256)
void k_in_gemm(const float* __restrict__ X, const float* __restrict__ thrp,
               const float* __restrict__ W1, const float* __restrict__ b1) {
    __shared__ float As[BK][BM+4];
    __shared__ float Bs[BK][BN+4];
    const int m0 = blockIdx.y * BM;
    const int n0 = blockIdx.x * BN;
    const int tid = threadIdx.x;
    const int tx = tid & 15, ty = tid >> 4;
    const float thr = *thrp;
    float acc[4][4] = {};
    for (int kc = 0; kc < 3; kc++) {
        for (int i = tid; i < BM*BK; i += 256) {
            int mi = i / BK, kk = i % BK;
            int m = m0 + mi;
            int t = m >> 7, b = m & 127;
            float xv = X[((b*3 + kc)*T_STEPS + t)*40 + kk];
            As[kk][mi] = (xv > thr) ? 1.0f : ((xv < -thr) ? -1.0f : 0.0f);
        }
        for (int i = tid; i < BN*BK; i += 256) {
            int ni = i / BK, kk = i % BK;
            Bs[kk][ni] = W1[(n0 + ni)*K_IN + kc*BK + kk];
        }
        __syncthreads();
        #pragma unroll
        for (int kk = 0; kk < BK; kk++) {
            float4 a4 = *(const float4*)&As[kk][ty*4];
            float4 b4 = *(const float4*)&Bs[kk][tx*4];
            float av[4] = {a4.x, a4.y, a4.z, a4.w};
            float bv[4] = {b4.x, b4.y, b4.z, b4.w};
            #pragma unroll
            for (int i = 0; i < 4; i++)
                #pragma unroll
                for (int j = 0; j < 4; j++)
                    acc[i][j] = fmaf(av[i], bv[j], acc[i][j]);
        }
        __syncthreads();
    }
    float4 bias = *(const float4*)&b1[n0 + tx*4];
    float bv[4] = {bias.x, bias.y, bias.z, bias.w};
    #pragma unroll
    for (int i = 0; i < 4; i++) {
        int row = m0 + ty*4 + i;
        float4 outv = make_float4(acc[i][0]+bv[0], acc[i][1]+bv[1],
                                  acc[i][2]+bv[2], acc[i][3]+bv[3]);
        *(float4*)&g_F[(size_t)row*HID + n0 + tx*4] = outv;
    }
}

// ---------------- K2: layer-1 LIF scan -> h-linear spike bitmasks -------------
__global__ __launch_bounds__(256)
void k_l1_scan(const float* __restrict__ tau_m1, const float* __restrict__ tau_adp1) {
    int idx = blockIdx.x * 256 + threadIdx.x;    // b*1024 + h
    int h = idx & 1023, b = idx >> 10;
    float alpha = expf(-1.0f / tau_m1[h]);
    float ro    = expf(-1.0f / tau_adp1[h]);
    float mem = 0.0f, spk = 0.0f, bb = 0.01f;
    int word = (h >> 5) & 31;
    int lane = threadIdx.x & 31;
    #pragma unroll 8
    for (int t = 0; t < T_STEPS; t++) {
        float x = __ldg(&g_F[(size_t)t*BH + idx]);
        bb = ro*bb + (1.0f - ro)*spk;
        float Bv = 0.01f + 1.8f*bb;
        mem = alpha*mem + (1.0f - alpha)*x - Bv*spk;
        spk = (mem - Bv > 0.0f) ? 1.0f : 0.0f;
        unsigned m = __ballot_sync(0xffffffffu, spk != 0.0f);
        if (lane == 0) g_m1[((size_t)b*T_STEPS + t)*32 + word] = m;
    }
}

// ---------------- K3: D = S1 @ Wd^T via mma.sync bf16 3-split -----------------
// grid (100 m-tiles of 256, 16 n-tiles of 64), 256 threads
// warps: wm = w&3 (64 rows each), wn = w>>2 (32 cols each); mf=4 m-frags/warp
__device__ __forceinline__ void mma16816(float* c, const unsigned* a, unsigned b0, unsigned b1) {
    asm volatile("mma.sync.aligned.m16n8k16.row.col.f32.bf16.bf16.f32 "
        "{%0,%1,%2,%3}, {%4,%5,%6,%7}, {%8,%9}, {%0,%1,%2,%3};"
        : "+f"(c[0]), "+f"(c[1]), "+f"(c[2]), "+f"(c[3])
        : "r"(a[0]), "r"(a[1]), "r"(a[2]), "r"(a[3]), "r"(b0), "r"(b1));
}
__device__ __forceinline__ unsigned spike_pack(unsigned m, int c) {
    return (((m >> c) & 1u) ? 0x3F80u : 0u) | (((m >> (c+1)) & 1u) ? 0x3F800000u : 0u);
}
__global__ __launch_bounds__(256, 1)
void k_dgemm() {
    __shared__ unsigned Bs[3][64][20];   // pad-20: conflict-free frag loads, 16B-aligned stage
    const int tid = threadIdx.x, lane = tid & 31, w = tid >> 5;
    const int wm = w & 3, wn = w >> 2;
    const int Mb = blockIdx.x * 256, Nb = blockIdx.y * 64;
    const int r = lane >> 2, t4 = lane & 3;
    float acc[4][4][4] = {};             // [m-frag][n-frag][reg]

    // mask row pointers: rows Mb + wm*64 + mf*16 + r + q*8
    const unsigned* mp[4][2];
    #pragma unroll
    for (int mf = 0; mf < 4; mf++)
        #pragma unroll
        for (int q = 0; q < 2; q++) {
            int m = Mb + wm*64 + mf*16 + r + q*8;
            int b = m & 127, t = m >> 7;
            mp[mf][q] = g_m1 + ((size_t)b*T_STEPS + t)*32;
        }
    const uint4* wdb4 = (const uint4*)g_WdB;   // 3 splits contiguous, uint4 view

    for (int kc = 0; kc < 32; kc++) {
        // stage B slice: 3 splits x 64 n x 16 words (32 bf16), uint4 granularity
        #pragma unroll
        for (int i = tid; i < 768; i += 256) {
            int s = i >> 8, rem = i & 255, n = rem >> 2, kq = rem & 3;
            uint4 v = __ldg(&wdb4[(size_t)s*131072 + (size_t)(Nb + n)*128 + kc*4 + kq]);
            *(uint4*)&Bs[s][n][kq*4] = v;
        }
        __syncthreads();
        unsigned mk[4][2];
        #pragma unroll
        for (int mf = 0; mf < 4; mf++) {
            mk[mf][0] = __ldg(&mp[mf][0][kc]);
            mk[mf][1] = __ldg(&mp[mf][1][kc]);
        }
        #pragma unroll
        for (int e = 0; e < 2; e++) {            // two k16 halves of the 32-chunk
            const int cb = e*16 + t4*2;
            unsigned a[4][4];
            #pragma unroll
            for (int mf = 0; mf < 4; mf++) {
                a[mf][0] = spike_pack(mk[mf][0], cb);
                a[mf][1] = spike_pack(mk[mf][1], cb);
                a[mf][2] = spike_pack(mk[mf][0], cb + 8);
                a[mf][3] = spike_pack(mk[mf][1], cb + 8);
            }
            #pragma unroll
            for (int s = 0; s < 3; s++)
                #pragma unroll
                for (int nf = 0; nf < 4; nf++) {
                    const unsigned* brow = Bs[s][wn*32 + nf*8 + r];
                    unsigned b0 = brow[e*8 + t4];
                    unsigned b1 = brow[e*8 + t4 + 4];
                    #pragma unroll
                    for (int mf = 0; mf < 4; mf++)
                        mma16816(acc[mf][nf], a[mf], b0, b1);
                }
        }
        __syncthreads();
    }
    // epilogue: D rows (t*128+b) match g_F layout
    #pragma unroll
    for (int mf = 0; mf < 4; mf++)
        #pragma unroll
        for (int nf = 0; nf < 4; nf++) {
            int col = Nb + wn*32 + nf*8 + t4*2;
            int row = Mb + wm*64 + mf*16 + r;
            *(float2*)&g_F[(size_t)row*HID + col] =
                make_float2(acc[mf][nf][0], acc[mf][nf][1]);
            *(float2*)&g_F[(size_t)(row + 8)*HID + col] =
                make_float2(acc[mf][nf][2], acc[mf][nf][3]);
        }
}

// ---------------- K4: persistent recurrent loop (1 block per batch) -----------
__global__ __launch_bounds__(256)
void k_steps(const float* __restrict__ tau_m_r, const float* __restrict__ tau_adp_r,
             const float* __restrict__ bd, const float* __restrict__ br) {
    __shared__ unsigned s_srm[32];
    __shared__ __align__(16) unsigned short list[1032];
    __shared__ int s_cnt[32];
    __shared__ int s_off[32];
    __shared__ int s_tot, s_n8;
    const int b = blockIdx.x, tid = threadIdx.x;
    const int lane = tid & 31, w = tid >> 5;
    const int j0 = tid * 4;

    float al[4], ro[4], bi[4], mem[4], bb[4], sp[4];
    #pragma unroll
    for (int i = 0; i < 4; i++) {
        al[i] = expf(-1.0f / tau_m_r[j0 + i]);
        ro[i] = expf(-1.0f / tau_adp_r[j0 + i]);
        bi[i] = bd[j0 + i] + br[j0 + i];
        mem[i] = 0.0f; bb[i] = 0.01f; sp[i] = 0.0f;
    }
    if (tid < 32) s_srm[tid] = 0u;
    __syncthreads();

    const float* wp = g_WrT + j0;                       // float4 slice per thread
    const float* fbase = g_F + (size_t)b*HID + j0;
    unsigned* mout = g_masks + (size_t)b*T_STEPS*32;

    for (int t = 0; t < T_STEPS; t++) {
        // 1. counts of active sr words
        unsigned myw = (tid < 32) ? s_srm[tid] : 0u;
        if (tid < 32) s_cnt[tid] = __popc(myw);
        __syncthreads();
        // 2. exclusive scan (warp 0)
        if (tid < 32) {
            int c = s_cnt[tid];
            int inc = c;
            #pragma unroll
            for (int d = 1; d < 32; d <<= 1) {
                int v = __shfl_up_sync(0xffffffffu, inc, d);
                if (lane >= d) inc += v;
            }
            s_off[tid] = inc - c;
            if (tid == 31) { s_tot = inc; s_n8 = (inc + 7) & ~7; }
        }
        __syncthreads();
        // 3. expand ballots into row list (ballot word v: h = (v>>2)*128 + l*4 + (v&3))
        if (tid < 32) {
            int o = s_off[tid];
            unsigned m = myw;
            int base = (tid >> 2)*128 + (tid & 3);
            while (m) {
                int l = __ffs(m) - 1; m &= m - 1;
                list[o++] = (unsigned short)(base + l*4);
            }
        }
        for (int i = s_tot + tid; i < s_n8; i += 256) list[i] = (unsigned short)1024;
        __syncthreads();
        // 4. fp32 gather over active rows
        const int n8 = s_n8;
        float4 f4 = *(const float4*)(fbase + (size_t)t*BH);
        float a0 = f4.x + bi[0], a1 = f4.y + bi[1], a2 = f4.z + bi[2], a3 = f4.w + bi[3];
        for (int i = 0; i < n8; i += 8) {
            uint4 u = *(const uint4*)&list[i];
            int e0 = u.x & 0xffff, e1 = u.x >> 16;
            int e2 = u.y & 0xffff, e3 = u.y >> 16;
            int e4 = u.z & 0xffff, e5 = u.z >> 16;
            int e6 = u.w & 0xffff, e7 = u.w >> 16;
            float4 v0 = *(const float4*)(wp + (size_t)e0*HID);
            float4 v1 = *(const float4*)(wp + (size_t)e1*HID);
            float4 v2 = *(const float4*)(wp + (size_t)e2*HID);
            float4 v3 = *(const float4*)(wp + (size_t)e3*HID);
            float4 v4 = *(const float4*)(wp + (size_t)e4*HID);
            float4 v5 = *(const float4*)(wp + (size_t)e5*HID);
            float4 v6 = *(const float4*)(wp + (size_t)e6*HID);
            float4 v7 = *(const float4*)(wp + (size_t)e7*HID);
            a0 += ((v0.x + v1.x) + (v2.x + v3.x)) + ((v4.x + v5.x) + (v6.x + v7.x));
            a1 += ((v0.y + v1.y) + (v2.y + v3.y)) + ((v4.y + v5.y) + (v6.y + v7.y));
            a2 += ((v0.z + v1.z) + (v2.z + v3.z)) + ((v4.z + v5.z) + (v6.z + v7.z));
            a3 += ((v0.w + v1.w) + (v2.w + v3.w)) + ((v4.w + v5.w) + (v6.w + v7.w));
        }
        float x[4] = {a0, a1, a2, a3};
        // 5. adaptive LIF update (4 neurons)
        #pragma unroll
        for (int i = 0; i < 4; i++) {
            bb[i] = ro[i]*bb[i] + (1.0f - ro[i])*sp[i];
            float Bv = 0.01f + 1.8f*bb[i];
            mem[i] = al[i]*mem[i] + (1.0f - al[i])*x[i] - Bv*sp[i];
            sp[i] = (mem[i] - Bv > 0.0f) ? 1.0f : 0.0f;
        }
        // 6. ballots -> smem (next step) + global (readout)
        #pragma unroll
        for (int i = 0; i < 4; i++) {
            unsigned m = __ballot_sync(0xffffffffu, sp[i] != 0.0f);
            if (lane == 0) {
                s_srm[w*4 + i] = m;
                mout[t*32 + w*4 + i] = m;
            }
        }
        __syncthreads();
    }
}

// ---------------- K5: readout + log_softmax -----------------------------------
__global__ __launch_bounds__(256)
void k_readout(const float* __restrict__ b2, float* __restrict__ out) {
    __shared__ float red[256][NOUT];
    __shared__ float vals[NOUT];
    __shared__ float s_l;
    const int b = blockIdx.x, tid = threadIdx.x;
    float acc[NOUT] = {};
    if (tid < T_STEPS) {
        float sum[NOUT] = {};
        const unsigned* gm = g_masks + ((size_t)b*T_STEPS + tid)*32;
        for (int v = 0; v < 32; v++) {
            unsigned m = gm[v];
            int base = (v >> 2)*128 + (v & 3);
            while (m) {
                int l = __ffs(m) - 1; m &= m - 1;
                const float* w2 = &g_W2T[(base + l*4)*NOUT];
                #pragma unroll
                for (int o = 0; o < NOUT; o++) sum[o] += w2[o];
            }
        }
        const float* c = &g_ctab[tid*NOUT];
        #pragma unroll
        for (int o = 0; o < NOUT; o++) acc[o] = c[o]*sum[o];
    }
    #pragma unroll
    for (int o = 0; o < NOUT; o++) red[tid][o] = acc[o];
    __syncthreads();
    for (int s = 128; s > 0; s >>= 1) {
        if (tid < s)
            #pragma unroll
            for (int o = 0; o < NOUT; o++) red[tid][o] += red[tid + s][o];
        __syncthreads();
    }
    if (tid < NOUT)
        vals[tid] = (red[0][tid] + g_csum[tid]*b2[tid]) * (1.0f / (float)T_STEPS);
    __syncthreads();
    if (tid == 0) {
        float m = vals[0];
        for (int o = 1; o < NOUT; o++) m = fmaxf(m, vals[o]);
        float s = 0.0f;
        for (int o = 0; o < NOUT; o++) s += expf(vals[o] - m);
        s_l = m + logf(s);
    }
    __syncthreads();
    if (tid < NOUT) out[b*NOUT + tid] = vals[tid] - s_l;
}

// ---------------- launch -------------------------------------------------------
extern "C" void kernel_launch(void* const* d_in, const int* in_sizes, int n_in,
                              void* d_out, int out_size) {
    const float* X        = (const float*)d_in[0];
    const float* thr      = (const float*)d_in[1];
    const float* W1       = (const float*)d_in[2];
    const float* b1       = (const float*)d_in[3];
    const float* Wd       = (const float*)d_in[4];
    const float* bd       = (const float*)d_in[5];
    const float* Wr       = (const float*)d_in[6];
    const float* br       = (const float*)d_in[7];
    const float* W2       = (const float*)d_in[8];
    const float* b2       = (const float*)d_in[9];
    const float* tau_m1   = (const float*)d_in[10];
    const float* tau_adp1 = (const float*)d_in[11];
    const float* tau_m_r  = (const float*)d_in[12];
    const float* tau_adp_r= (const float*)d_in[13];
    const float* tau_m2   = (const float*)d_in[14];
    float* out = (float*)d_out;

    k_prep<<<(HID*HID + 255)/256, 256>>>(Wd, Wr, W2, tau_m2);
    k_in_gemm<<<dim3(HID/BN, NROWS/BM), 256>>>(X, thr, W1, b1);
    k_l1_scan<<<BH/256, 256>>>(tau_m1, tau_adp1);
    k_dgemm<<<dim3(100, 16), 256>>>();
    k_steps<<<BATCH, 256>>>(tau_m_r, tau_adp_r, bd, br);
    k_readout<<<BATCH, 256>>>(b2, out);
}

// round 7
// speedup vs baseline: 4.1256x; 1.0848x over previous
#include <cuda_runtime.h>
#include <cuda_bf16.h>
#include <math.h>

#define T_STEPS 200
#define BATCH   128
#define HID     1024
#define K_IN    120
#define NOUT    12
#define BH      (BATCH*HID)      // 131072
#define NROWS   (T_STEPS*BATCH)  // 25600

// ---------------- static device scratch (no allocations allowed) ------------
__device__ float          g_F[NROWS*HID];       // W1 drive, then overwritten by D = S1@Wd^T
__device__ float          g_WrT[1025*HID];      // Wr^T fp32 [h][j] + zero pad row
__device__ __nv_bfloat16  g_WdB[3][HID*HID];    // Wd 3-way bf16 split, [j][h] native layout
__device__ float          g_W2T[HID*NOUT];
__device__ unsigned       g_m1[(size_t)BATCH*T_STEPS*32];    // layer-1 spike masks (h-linear)
__device__ unsigned       g_masks[(size_t)BATCH*T_STEPS*32]; // recurrent spike ballots
__device__ float          g_ctab[T_STEPS*NOUT];
__device__ float          g_csum[NOUT];

// ---------------- prep: Wr transpose, Wd 3-split, W2T, tables ----------------
__global__ __launch_bounds__(256)
void k_prep(const float* __restrict__ Wd, const float* __restrict__ Wr,
            const float* __restrict__ W2, const float* __restrict__ tau_m2) {
    int idx = blockIdx.x * 256 + threadIdx.x;
    if (idx < HID*HID) {
        int j = idx >> 10, h = idx & 1023;
        g_WrT[(size_t)h*HID + j] = Wr[idx];      // Wr^T[h][j]
        float w = Wd[idx];
        __nv_bfloat16 h1 = __float2bfloat16(w);
        float r1 = w - __bfloat162float(h1);
        __nv_bfloat16 h2 = __float2bfloat16(r1);
        float r2 = r1 - __bfloat162float(h2);
        __nv_bfloat16 h3 = __float2bfloat16(r2);
        g_WdB[0][idx] = h1;
        g_WdB[1][idx] = h2;
        g_WdB[2][idx] = h3;
    }
    if (idx < HID*NOUT) {
        int h = idx / NOUT, o = idx % NOUT;
        g_W2T[idx] = W2[o*HID + h];
    }
    if (idx < T_STEPS*NOUT) {
        int k = idx / NOUT, o = idx % NOUT;
        float a2 = expf(-1.0f / tau_m2[o]);
        g_ctab[idx] = 1.0f - powf(a2, (float)(T_STEPS - k));
    }
    if (idx < NOUT) {
        float a2 = expf(-1.0f / tau_m2[idx]);
        float s = 0.0f, p = 1.0f;
        for (int n = 1; n <= T_STEPS; n++) { p *= a2; s += p; }
        g_csum[idx] = (float)T_STEPS - s;
    }
    if (idx < HID) g_WrT[(size_t)1024*HID + idx] = 0.0f;   // zero pad row
}

// ---------------- K1: F = ternary(X) @ W1^T + b1 ------------------------------
#define BM 64
#define BN 64
#define BK 40
__global__ __launch_bounds__(256)
void k_in_gemm(const float* __restrict__ X, const float* __restrict__ thrp,
               const float* __restrict__ W1, const float* __restrict__ b1) {
    __shared__ float As[BK][BM+4];
    __shared__ float Bs[BK][BN+4];
    const int m0 = blockIdx.y * BM;
    const int n0 = blockIdx.x * BN;
    const int tid = threadIdx.x;
    const int tx = tid & 15, ty = tid >> 4;
    const float thr = *thrp;
    float acc[4][4] = {};
    for (int kc = 0; kc < 3; kc++) {
        for (int i = tid; i < BM*BK; i += 256) {
            int mi = i / BK, kk = i % BK;
            int m = m0 + mi;
            int t = m >> 7, b = m & 127;
            float xv = X[((b*3 + kc)*T_STEPS + t)*40 + kk];
            As[kk][mi] = (xv > thr) ? 1.0f : ((xv < -thr) ? -1.0f : 0.0f);
        }
        for (int i = tid; i < BN*BK; i += 256) {
            int ni = i / BK, kk = i % BK;
            Bs[kk][ni] = W1[(n0 + ni)*K_IN + kc*BK + kk];
        }
        __syncthreads();
        #pragma unroll
        for (int kk = 0; kk < BK; kk++) {
            float4 a4 = *(const float4*)&As[kk][ty*4];
            float4 b4 = *(const float4*)&Bs[kk][tx*4];
            float av[4] = {a4.x, a4.y, a4.z, a4.w};
            float bv[4] = {b4.x, b4.y, b4.z, b4.w};
            #pragma unroll
            for (int i = 0; i < 4; i++)
                #pragma unroll
                for (int j = 0; j < 4; j++)
                    acc[i][j] = fmaf(av[i], bv[j], acc[i][j]);
        }
        __syncthreads();
    }
    float4 bias = *(const float4*)&b1[n0 + tx*4];
    float bv[4] = {bias.x, bias.y, bias.z, bias.w};
    #pragma unroll
    for (int i = 0; i < 4; i++) {
        int row = m0 + ty*4 + i;
        float4 outv = make_float4(acc[i][0]+bv[0], acc[i][1]+bv[1],
                                  acc[i][2]+bv[2], acc[i][3]+bv[3]);
        *(float4*)&g_F[(size_t)row*HID + n0 + tx*4] = outv;
    }
}

// ---------------- K2: layer-1 LIF scan -> h-linear spike bitmasks -------------
__global__ __launch_bounds__(256)
void k_l1_scan(const float* __restrict__ tau_m1, const float* __restrict__ tau_adp1) {
    int idx = blockIdx.x * 256 + threadIdx.x;    // b*1024 + h
    int h = idx & 1023, b = idx >> 10;
    float alpha = expf(-1.0f / tau_m1[h]);
    float ro    = expf(-1.0f / tau_adp1[h]);
    float mem = 0.0f, spk = 0.0f, bb = 0.01f;
    int word = (h >> 5) & 31;
    int lane = threadIdx.x & 31;
    #pragma unroll 8
    for (int t = 0; t < T_STEPS; t++) {
        float x = __ldg(&g_F[(size_t)t*BH + idx]);
        bb = ro*bb + (1.0f - ro)*spk;
        float Bv = 0.01f + 1.8f*bb;
        mem = alpha*mem + (1.0f - alpha)*x - Bv*spk;
        spk = (mem - Bv > 0.0f) ? 1.0f : 0.0f;
        unsigned m = __ballot_sync(0xffffffffu, spk != 0.0f);
        if (lane == 0) g_m1[((size_t)b*T_STEPS + t)*32 + word] = m;
    }
}

// ---------------- K3: D = S1 @ Wd^T via mma.sync bf16 3-split -----------------
// grid (100 m-tiles of 256, 16 n-tiles of 64), 256 threads
// Register-staged pipeline: iteration kc+1's B uint4s + A mask words are
// prefetched into registers before the kc mma block, hiding LDG latency.
__device__ __forceinline__ void mma16816(float* c, const unsigned* a, unsigned b0, unsigned b1) {
    asm volatile("mma.sync.aligned.m16n8k16.row.col.f32.bf16.bf16.f32 "
        "{%0,%1,%2,%3}, {%4,%5,%6,%7}, {%8,%9}, {%0,%1,%2,%3};"
        : "+f"(c[0]), "+f"(c[1]), "+f"(c[2]), "+f"(c[3])
        : "r"(a[0]), "r"(a[1]), "r"(a[2]), "r"(a[3]), "r"(b0), "r"(b1));
}
__device__ __forceinline__ unsigned spike_pack(unsigned m, int c) {
    return (((m >> c) & 1u) ? 0x3F80u : 0u) | (((m >> (c+1)) & 1u) ? 0x3F800000u : 0u);
}
__global__ __launch_bounds__(256, 1)
void k_dgemm() {
    __shared__ unsigned Bs[3][64][20];   // pad-20: conflict-free frag loads
    const int tid = threadIdx.x, lane = tid & 31, w = tid >> 5;
    const int wm = w & 3, wn = w >> 2;
    const int Mb = blockIdx.x * 256, Nb = blockIdx.y * 64;
    const int r = lane >> 2, t4 = lane & 3;
    float acc[4][4][4] = {};             // [m-frag][n-frag][reg]

    // each thread owns B slot (n = tid>>2, kq = tid&3) for all 3 splits
    const int bn = tid >> 2, bkq = tid & 3;
    const uint4* bsrc[3];
    #pragma unroll
    for (int s = 0; s < 3; s++)
        bsrc[s] = (const uint4*)g_WdB + (size_t)s*131072 + (size_t)(Nb + bn)*128 + bkq;

    // mask row pointers: rows Mb + wm*64 + mf*16 + r + q*8
    const unsigned* mp[4][2];
    #pragma unroll
    for (int mf = 0; mf < 4; mf++)
        #pragma unroll
        for (int q = 0; q < 2; q++) {
            int m = Mb + wm*64 + mf*16 + r + q*8;
            int b = m & 127, t = m >> 7;
            mp[mf][q] = g_m1 + ((size_t)b*T_STEPS + t)*32;
        }

    // preload iteration 0
    uint4 v[3];
    unsigned mk[4][2];
    #pragma unroll
    for (int s = 0; s < 3; s++) v[s] = __ldg(bsrc[s]);
    #pragma unroll
    for (int mf = 0; mf < 4; mf++) {
        mk[mf][0] = __ldg(&mp[mf][0][0]);
        mk[mf][1] = __ldg(&mp[mf][1][0]);
    }

    for (int kc = 0; kc < 32; kc++) {
        // commit staged B to smem
        #pragma unroll
        for (int s = 0; s < 3; s++) *(uint4*)&Bs[s][bn][bkq*4] = v[s];
        __syncthreads();

        // prefetch next iteration (latency hidden behind the mma block)
        uint4 vn[3];
        unsigned mkn[4][2];
        if (kc < 31) {
            #pragma unroll
            for (int s = 0; s < 3; s++) vn[s] = __ldg(bsrc[s] + (kc + 1)*4);
            #pragma unroll
            for (int mf = 0; mf < 4; mf++) {
                mkn[mf][0] = __ldg(&mp[mf][0][kc + 1]);
                mkn[mf][1] = __ldg(&mp[mf][1][kc + 1]);
            }
        }

        #pragma unroll
        for (int e = 0; e < 2; e++) {            // two k16 halves of the 32-chunk
            const int cb = e*16 + t4*2;
            unsigned a[4][4];
            #pragma unroll
            for (int mf = 0; mf < 4; mf++) {
                a[mf][0] = spike_pack(mk[mf][0], cb);
                a[mf][1] = spike_pack(mk[mf][1], cb);
                a[mf][2] = spike_pack(mk[mf][0], cb + 8);
                a[mf][3] = spike_pack(mk[mf][1], cb + 8);
            }
            #pragma unroll
            for (int s = 0; s < 3; s++)
                #pragma unroll
                for (int nf = 0; nf < 4; nf++) {
                    const unsigned* brow = Bs[s][wn*32 + nf*8 + r];
                    unsigned b0 = brow[e*8 + t4];
                    unsigned b1 = brow[e*8 + t4 + 4];
                    #pragma unroll
                    for (int mf = 0; mf < 4; mf++)
                        mma16816(acc[mf][nf], a[mf], b0, b1);
                }
        }
        __syncthreads();
        #pragma unroll
        for (int s = 0; s < 3; s++) v[s] = vn[s];
        #pragma unroll
        for (int mf = 0; mf < 4; mf++) {
            mk[mf][0] = mkn[mf][0];
            mk[mf][1] = mkn[mf][1];
        }
    }
    // epilogue: D rows (t*128+b) match g_F layout
    #pragma unroll
    for (int mf = 0; mf < 4; mf++)
        #pragma unroll
        for (int nf = 0; nf < 4; nf++) {
            int col = Nb + wn*32 + nf*8 + t4*2;
            int row = Mb + wm*64 + mf*16 + r;
            *(float2*)&g_F[(size_t)row*HID + col] =
                make_float2(acc[mf][nf][0], acc[mf][nf][1]);
            *(float2*)&g_F[(size_t)(row + 8)*HID + col] =
                make_float2(acc[mf][nf][2], acc[mf][nf][3]);
        }
}

// ---------------- K4: persistent recurrent loop (1 block per batch) -----------
__global__ __launch_bounds__(256)
void k_steps(const float* __restrict__ tau_m_r, const float* __restrict__ tau_adp_r,
             const float* __restrict__ bd, const float* __restrict__ br) {
    __shared__ unsigned s_srm[32];
    __shared__ __align__(16) unsigned short list[1032];
    __shared__ int s_cnt[32];
    __shared__ int s_off[32];
    __shared__ int s_tot, s_n8;
    const int b = blockIdx.x, tid = threadIdx.x;
    const int lane = tid & 31, w = tid >> 5;
    const int j0 = tid * 4;

    float al[4], ro[4], bi[4], mem[4], bb[4], sp[4];
    #pragma unroll
    for (int i = 0; i < 4; i++) {
        al[i] = expf(-1.0f / tau_m_r[j0 + i]);
        ro[i] = expf(-1.0f / tau_adp_r[j0 + i]);
        bi[i] = bd[j0 + i] + br[j0 + i];
        mem[i] = 0.0f; bb[i] = 0.01f; sp[i] = 0.0f;
    }
    if (tid < 32) s_srm[tid] = 0u;
    __syncthreads();

    const float* wp = g_WrT + j0;                       // float4 slice per thread
    const float* fbase = g_F + (size_t)b*HID + j0;
    unsigned* mout = g_masks + (size_t)b*T_STEPS*32;

    for (int t = 0; t < T_STEPS; t++) {
        // 1. counts of active sr words
        unsigned myw = (tid < 32) ? s_srm[tid] : 0u;
        if (tid < 32) s_cnt[tid] = __popc(myw);
        __syncthreads();
        // 2. exclusive scan (warp 0)
        if (tid < 32) {
            int c = s_cnt[tid];
            int inc = c;
            #pragma unroll
            for (int d = 1; d < 32; d <<= 1) {
                int v = __shfl_up_sync(0xffffffffu, inc, d);
                if (lane >= d) inc += v;
            }
            s_off[tid] = inc - c;
            if (tid == 31) { s_tot = inc; s_n8 = (inc + 7) & ~7; }
        }
        __syncthreads();
        // 3. expand ballots into row list (ballot word v: h = (v>>2)*128 + l*4 + (v&3))
        if (tid < 32) {
            int o = s_off[tid];
            unsigned m = myw;
            int base = (tid >> 2)*128 + (tid & 3);
            while (m) {
                int l = __ffs(m) - 1; m &= m - 1;
                list[o++] = (unsigned short)(base + l*4);
            }
        }
        for (int i = s_tot + tid; i < s_n8; i += 256) list[i] = (unsigned short)1024;
        __syncthreads();
        // 4. fp32 gather over active rows
        const int n8 = s_n8;
        float4 f4 = *(const float4*)(fbase + (size_t)t*BH);
        float a0 = f4.x + bi[0], a1 = f4.y + bi[1], a2 = f4.z + bi[2], a3 = f4.w + bi[3];
        for (int i = 0; i < n8; i += 8) {
            uint4 u = *(const uint4*)&list[i];
            int e0 = u.x & 0xffff, e1 = u.x >> 16;
            int e2 = u.y & 0xffff, e3 = u.y >> 16;
            int e4 = u.z & 0xffff, e5 = u.z >> 16;
            int e6 = u.w & 0xffff, e7 = u.w >> 16;
            float4 v0 = *(const float4*)(wp + (size_t)e0*HID);
            float4 v1 = *(const float4*)(wp + (size_t)e1*HID);
            float4 v2 = *(const float4*)(wp + (size_t)e2*HID);
            float4 v3 = *(const float4*)(wp + (size_t)e3*HID);
            float4 v4 = *(const float4*)(wp + (size_t)e4*HID);
            float4 v5 = *(const float4*)(wp + (size_t)e5*HID);
            float4 v6 = *(const float4*)(wp + (size_t)e6*HID);
            float4 v7 = *(const float4*)(wp + (size_t)e7*HID);
            a0 += ((v0.x + v1.x) + (v2.x + v3.x)) + ((v4.x + v5.x) + (v6.x + v7.x));
            a1 += ((v0.y + v1.y) + (v2.y + v3.y)) + ((v4.y + v5.y) + (v6.y + v7.y));
            a2 += ((v0.z + v1.z) + (v2.z + v3.z)) + ((v4.z + v5.z) + (v6.z + v7.z));
            a3 += ((v0.w + v1.w) + (v2.w + v3.w)) + ((v4.w + v5.w) + (v6.w + v7.w));
        }
        float x[4] = {a0, a1, a2, a3};
        // 5. adaptive LIF update (4 neurons)
        #pragma unroll
        for (int i = 0; i < 4; i++) {
            bb[i] = ro[i]*bb[i] + (1.0f - ro[i])*sp[i];
            float Bv = 0.01f + 1.8f*bb[i];
            mem[i] = al[i]*mem[i] + (1.0f - al[i])*x[i] - Bv*sp[i];
            sp[i] = (mem[i] - Bv > 0.0f) ? 1.0f : 0.0f;
        }
        // 6. ballots -> smem (next step) + global (readout)
        #pragma unroll
        for (int i = 0; i < 4; i++) {
            unsigned m = __ballot_sync(0xffffffffu, sp[i] != 0.0f);
            if (lane == 0) {
                s_srm[w*4 + i] = m;
                mout[t*32 + w*4 + i] = m;
            }
        }
        __syncthreads();
    }
}

// ---------------- K5: readout + log_softmax -----------------------------------
__global__ __launch_bounds__(256)
void k_readout(const float* __restrict__ b2, float* __restrict__ out) {
    __shared__ float red[256][NOUT];
    __shared__ float vals[NOUT];
    __shared__ float s_l;
    const int b = blockIdx.x, tid = threadIdx.x;
    float acc[NOUT] = {};
    if (tid < T_STEPS) {
        float sum[NOUT] = {};
        const unsigned* gm = g_masks + ((size_t)b*T_STEPS + tid)*32;
        for (int v = 0; v < 32; v++) {
            unsigned m = gm[v];
            int base = (v >> 2)*128 + (v & 3);
            while (m) {
                int l = __ffs(m) - 1; m &= m - 1;
                const float* w2 = &g_W2T[(base + l*4)*NOUT];
                #pragma unroll
                for (int o = 0; o < NOUT; o++) sum[o] += w2[o];
            }
        }
        const float* c = &g_ctab[tid*NOUT];
        #pragma unroll
        for (int o = 0; o < NOUT; o++) acc[o] = c[o]*sum[o];
    }
    #pragma unroll
    for (int o = 0; o < NOUT; o++) red[tid][o] = acc[o];
    __syncthreads();
    for (int s = 128; s > 0; s >>= 1) {
        if (tid < s)
            #pragma unroll
            for (int o = 0; o < NOUT; o++) red[tid][o] += red[tid + s][o];
        __syncthreads();
    }
    if (tid < NOUT)
        vals[tid] = (red[0][tid] + g_csum[tid]*b2[tid]) * (1.0f / (float)T_STEPS);
    __syncthreads();
    if (tid == 0) {
        float m = vals[0];
        for (int o = 1; o < NOUT; o++) m = fmaxf(m, vals[o]);
        float s = 0.0f;
        for (int o = 0; o < NOUT; o++) s += expf(vals[o] - m);
        s_l = m + logf(s);
    }
    __syncthreads();
    if (tid < NOUT) out[b*NOUT + tid] = vals[tid] - s_l;
}

// ---------------- launch -------------------------------------------------------
extern "C" void kernel_launch(void* const* d_in, const int* in_sizes, int n_in,
                              void* d_out, int out_size) {
    const float* X        = (const float*)d_in[0];
    const float* thr      = (const float*)d_in[1];
    const float* W1       = (const float*)d_in[2];
    const float* b1       = (const float*)d_in[3];
    const float* Wd       = (const float*)d_in[4];
    const float* bd       = (const float*)d_in[5];
    const float* Wr       = (const float*)d_in[6];
    const float* br       = (const float*)d_in[7];
    const float* W2       = (const float*)d_in[8];
    const float* b2       = (const float*)d_in[9];
    const float* tau_m1   = (const float*)d_in[10];
    const float* tau_adp1 = (const float*)d_in[11];
    const float* tau_m_r  = (const float*)d_in[12];
    const float* tau_adp_r= (const float*)d_in[13];
    const float* tau_m2   = (const float*)d_in[14];
    float* out = (float*)d_out;

    k_prep<<<(HID*HID + 255)/256, 256>>>(Wd, Wr, W2, tau_m2);
    k_in_gemm<<<dim3(HID/BN, NROWS/BM), 256>>>(X, thr, W1, b1);
    k_l1_scan<<<BH/256, 256>>>(tau_m1, tau_adp1);
    k_dgemm<<<dim3(100, 16), 256>>>();
    k_steps<<<BATCH, 256>>>(tau_m_r, tau_adp_r, bd, br);
    k_readout<<<BATCH, 256>>>(b2, out);
}

// round 8
// speedup vs baseline: 4.3319x; 1.0500x over previous
#include <cuda_runtime.h>
#include <cuda_bf16.h>
#include <math.h>

#define T_STEPS 200
#define BATCH   128
#define HID     1024
#define K_IN    120
#define NOUT    12
#define BH      (BATCH*HID)      // 131072
#define NROWS   (T_STEPS*BATCH)  // 25600

// ---------------- static device scratch (no allocations allowed) ------------
__device__ float          g_F[NROWS*HID];       // W1 drive, then overwritten by D = S1@Wd^T
__device__ float          g_WrT[1025*HID];      // Wr^T fp32 [h][j] + zero pad row
__device__ __nv_bfloat16  g_WdB[3][HID*HID];    // Wd 3-way bf16 split, [j][h] native layout
__device__ float          g_W2T[HID*NOUT];
__device__ unsigned       g_m1[(size_t)BATCH*T_STEPS*32];    // layer-1 spike masks (h-linear)
__device__ unsigned       g_masks[(size_t)BATCH*T_STEPS*32]; // recurrent spike ballots
__device__ float          g_ctab[T_STEPS*NOUT];
__device__ float          g_csum[NOUT];

// ---------------- prep: Wr transpose, Wd 3-split, W2T, tables ----------------
__global__ __launch_bounds__(256)
void k_prep(const float* __restrict__ Wd, const float* __restrict__ Wr,
            const float* __restrict__ W2, const float* __restrict__ tau_m2) {
    int idx = blockIdx.x * 256 + threadIdx.x;
    if (idx < HID*HID) {
        int j = idx >> 10, h = idx & 1023;
        g_WrT[(size_t)h*HID + j] = Wr[idx];      // Wr^T[h][j]
        float w = Wd[idx];
        __nv_bfloat16 h1 = __float2bfloat16(w);
        float r1 = w - __bfloat162float(h1);
        __nv_bfloat16 h2 = __float2bfloat16(r1);
        float r2 = r1 - __bfloat162float(h2);
        __nv_bfloat16 h3 = __float2bfloat16(r2);
        g_WdB[0][idx] = h1;
        g_WdB[1][idx] = h2;
        g_WdB[2][idx] = h3;
    }
    if (idx < HID*NOUT) {
        int h = idx / NOUT, o = idx % NOUT;
        g_W2T[idx] = W2[o*HID + h];
    }
    if (idx < T_STEPS*NOUT) {
        int k = idx / NOUT, o = idx % NOUT;
        float a2 = expf(-1.0f / tau_m2[o]);
        g_ctab[idx] = 1.0f - powf(a2, (float)(T_STEPS - k));
    }
    if (idx < NOUT) {
        float a2 = expf(-1.0f / tau_m2[idx]);
        float s = 0.0f, p = 1.0f;
        for (int n = 1; n <= T_STEPS; n++) { p *= a2; s += p; }
        g_csum[idx] = (float)T_STEPS - s;
    }
    if (idx < HID) g_WrT[(size_t)1024*HID + idx] = 0.0f;   // zero pad row
}

// ---------------- K1: F = ternary(X) @ W1^T + b1 ------------------------------
#define BM 64
#define BN 64
#define BK 40
__global__ __launch_bounds__(256)
void k_in_gemm(const float* __restrict__ X, const float* __restrict__ thrp,
               const float* __restrict__ W1, const float* __restrict__ b1) {
    __shared__ float As[BK][BM+4];
    __shared__ float Bs[BK][BN+4];
    const int m0 = blockIdx.y * BM;
    const int n0 = blockIdx.x * BN;
    const int tid = threadIdx.x;
    const int tx = tid & 15, ty = tid >> 4;
    const float thr = *thrp;
    float acc[4][4] = {};
    for (int kc = 0; kc < 3; kc++) {
        for (int i = tid; i < BM*BK; i += 256) {
            int mi = i / BK, kk = i % BK;
            int m = m0 + mi;
            int t = m >> 7, b = m & 127;
            float xv = X[((b*3 + kc)*T_STEPS + t)*40 + kk];
            As[kk][mi] = (xv > thr) ? 1.0f : ((xv < -thr) ? -1.0f : 0.0f);
        }
        for (int i = tid; i < BN*BK; i += 256) {
            int ni = i / BK, kk = i % BK;
            Bs[kk][ni] = W1[(n0 + ni)*K_IN + kc*BK + kk];
        }
        __syncthreads();
        #pragma unroll
        for (int kk = 0; kk < BK; kk++) {
            float4 a4 = *(const float4*)&As[kk][ty*4];
            float4 b4 = *(const float4*)&Bs[kk][tx*4];
            float av[4] = {a4.x, a4.y, a4.z, a4.w};
            float bv[4] = {b4.x, b4.y, b4.z, b4.w};
            #pragma unroll
            for (int i = 0; i < 4; i++)
                #pragma unroll
                for (int j = 0; j < 4; j++)
                    acc[i][j] = fmaf(av[i], bv[j], acc[i][j]);
        }
        __syncthreads();
    }
    float4 bias = *(const float4*)&b1[n0 + tx*4];
    float bv[4] = {bias.x, bias.y, bias.z, bias.w};
    #pragma unroll
    for (int i = 0; i < 4; i++) {
        int row = m0 + ty*4 + i;
        float4 outv = make_float4(acc[i][0]+bv[0], acc[i][1]+bv[1],
                                  acc[i][2]+bv[2], acc[i][3]+bv[3]);
        *(float4*)&g_F[(size_t)row*HID + n0 + tx*4] = outv;
    }
}

// ---------------- K2: layer-1 LIF scan -> h-linear spike bitmasks -------------
__global__ __launch_bounds__(256)
void k_l1_scan(const float* __restrict__ tau_m1, const float* __restrict__ tau_adp1) {
    int idx = blockIdx.x * 256 + threadIdx.x;    // b*1024 + h
    int h = idx & 1023, b = idx >> 10;
    float alpha = expf(-1.0f / tau_m1[h]);
    float ro    = expf(-1.0f / tau_adp1[h]);
    float mem = 0.0f, spk = 0.0f, bb = 0.01f;
    int word = (h >> 5) & 31;
    int lane = threadIdx.x & 31;
    #pragma unroll 8
    for (int t = 0; t < T_STEPS; t++) {
        float x = __ldg(&g_F[(size_t)t*BH + idx]);
        bb = ro*bb + (1.0f - ro)*spk;
        float Bv = 0.01f + 1.8f*bb;
        mem = alpha*mem + (1.0f - alpha)*x - Bv*spk;
        spk = (mem - Bv > 0.0f) ? 1.0f : 0.0f;
        unsigned m = __ballot_sync(0xffffffffu, spk != 0.0f);
        if (lane == 0) g_m1[((size_t)b*T_STEPS + t)*32 + word] = m;
    }
}

// ---------------- K3: D = S1 @ Wd^T via mma.sync bf16 3-split -----------------
// grid (200 m-tiles of 128 = one timestep, 16 n-tiles of 64), 128 threads.
// 4 warps: wm = w&1 (64 rows), wn = w>>1 (32 cols); mf=4, nf=4.
// Double-buffered cp.async B staging, one __syncthreads per k-chunk.
__device__ __forceinline__ void mma16816(float* c, const unsigned* a, unsigned b0, unsigned b1) {
    asm volatile("mma.sync.aligned.m16n8k16.row.col.f32.bf16.bf16.f32 "
        "{%0,%1,%2,%3}, {%4,%5,%6,%7}, {%8,%9}, {%0,%1,%2,%3};"
        : "+f"(c[0]), "+f"(c[1]), "+f"(c[2]), "+f"(c[3])
        : "r"(a[0]), "r"(a[1]), "r"(a[2]), "r"(a[3]), "r"(b0), "r"(b1));
}
__device__ __forceinline__ unsigned spike_pack(unsigned m, int c) {
    return (((m >> c) & 1u) ? 0x3F80u : 0u) | (((m >> (c+1)) & 1u) ? 0x3F800000u : 0u);
}
__device__ __forceinline__ void cp16(unsigned dst, const void* src) {
    asm volatile("cp.async.cg.shared.global [%0], [%1], 16;" :: "r"(dst), "l"(src) : "memory");
}
__global__ __launch_bounds__(128, 3)
void k_dgemm() {
    __shared__ unsigned Bs[2][3][64][20];   // double buffer, pad-20 conflict-free
    const int tid = threadIdx.x, lane = tid & 31, w = tid >> 5;
    const int wm = w & 1, wn = w >> 1;
    const int tt = blockIdx.x, Nb = blockIdx.y * 64;   // M-tile = timestep tt
    const int r = lane >> 2, t4 = lane & 3;
    float acc[4][4][4] = {};             // [m-frag][n-frag][reg]

    const uint4* wdb4 = (const uint4*)g_WdB;
    const unsigned sb = (unsigned)__cvta_generic_to_shared(Bs);

    // mask row pointers: rows b = wm*64 + mf*16 + r + q*8, all at timestep tt
    const unsigned* mp[4][2];
    #pragma unroll
    for (int mf = 0; mf < 4; mf++)
        #pragma unroll
        for (int q = 0; q < 2; q++) {
            int b = wm*64 + mf*16 + r + q*8;
            mp[mf][q] = g_m1 + ((size_t)b*T_STEPS + tt)*32;
        }

    // stage one k-chunk of B (3 splits x 64 n x 16 words) into buffer `buf`
    auto stage = [&](int kc, int buf) {
        #pragma unroll
        for (int i = tid; i < 768; i += 128) {        // 6 cp.async of 16B per thread
            int s = i >> 8, rem = i & 255, n = rem >> 2, kq = rem & 3;
            unsigned dst = sb + (unsigned)((((buf*3 + s)*64 + n)*20 + kq*4)*4);
            cp16(dst, wdb4 + (size_t)s*131072 + (size_t)(Nb + n)*128 + kc*4 + kq);
        }
        asm volatile("cp.async.commit_group;" ::: "memory");
    };

    stage(0, 0);
    unsigned mk[4][2];
    #pragma unroll
    for (int mf = 0; mf < 4; mf++) {
        mk[mf][0] = __ldg(&mp[mf][0][0]);
        mk[mf][1] = __ldg(&mp[mf][1][0]);
    }

    for (int kc = 0; kc < 32; kc++) {
        asm volatile("cp.async.wait_group 0;" ::: "memory");
        __syncthreads();                               // buf[kc&1] ready, prior reads done
        if (kc < 31) stage(kc + 1, (kc + 1) & 1);      // fills other buffer during compute

        unsigned mkn[4][2];
        if (kc < 31) {
            #pragma unroll
            for (int mf = 0; mf < 4; mf++) {
                mkn[mf][0] = __ldg(&mp[mf][0][kc + 1]);
                mkn[mf][1] = __ldg(&mp[mf][1][kc + 1]);
            }
        }

        const int buf = kc & 1;
        #pragma unroll
        for (int e = 0; e < 2; e++) {                  // two k16 halves of the 32-chunk
            const int cb = e*16 + t4*2;
            unsigned a[4][4];
            #pragma unroll
            for (int mf = 0; mf < 4; mf++) {
                a[mf][0] = spike_pack(mk[mf][0], cb);
                a[mf][1] = spike_pack(mk[mf][1], cb);
                a[mf][2] = spike_pack(mk[mf][0], cb + 8);
                a[mf][3] = spike_pack(mk[mf][1], cb + 8);
            }
            #pragma unroll
            for (int s = 0; s < 3; s++)
                #pragma unroll
                for (int nf = 0; nf < 4; nf++) {
                    const unsigned* brow = Bs[buf][s][wn*32 + nf*8 + r];
                    unsigned b0 = brow[e*8 + t4];
                    unsigned b1 = brow[e*8 + t4 + 4];
                    #pragma unroll
                    for (int mf = 0; mf < 4; mf++)
                        mma16816(acc[mf][nf], a[mf], b0, b1);
                }
        }
        #pragma unroll
        for (int mf = 0; mf < 4; mf++) {
            mk[mf][0] = mkn[mf][0];
            mk[mf][1] = mkn[mf][1];
        }
    }
    // epilogue: D rows (tt*128 + b) match g_F layout
    #pragma unroll
    for (int mf = 0; mf < 4; mf++)
        #pragma unroll
        for (int nf = 0; nf < 4; nf++) {
            int col = Nb + wn*32 + nf*8 + t4*2;
            int row = tt*128 + wm*64 + mf*16 + r;
            *(float2*)&g_F[(size_t)row*HID + col] =
                make_float2(acc[mf][nf][0], acc[mf][nf][1]);
            *(float2*)&g_F[(size_t)(row + 8)*HID + col] =
                make_float2(acc[mf][nf][2], acc[mf][nf][3]);
        }
}

// ---------------- K4: persistent recurrent loop (1 block per batch) -----------
__global__ __launch_bounds__(256)
void k_steps(const float* __restrict__ tau_m_r, const float* __restrict__ tau_adp_r,
             const float* __restrict__ bd, const float* __restrict__ br) {
    __shared__ unsigned s_srm[32];
    __shared__ __align__(16) unsigned short list[1032];
    __shared__ int s_cnt[32];
    __shared__ int s_off[32];
    __shared__ int s_tot, s_n8;
    const int b = blockIdx.x, tid = threadIdx.x;
    const int lane = tid & 31, w = tid >> 5;
    const int j0 = tid * 4;

    float al[4], ro[4], bi[4], mem[4], bb[4], sp[4];
    #pragma unroll
    for (int i = 0; i < 4; i++) {
        al[i] = expf(-1.0f / tau_m_r[j0 + i]);
        ro[i] = expf(-1.0f / tau_adp_r[j0 + i]);
        bi[i] = bd[j0 + i] + br[j0 + i];
        mem[i] = 0.0f; bb[i] = 0.01f; sp[i] = 0.0f;
    }
    if (tid < 32) s_srm[tid] = 0u;
    __syncthreads();

    const float* wp = g_WrT + j0;                       // float4 slice per thread
    const float* fbase = g_F + (size_t)b*HID + j0;
    unsigned* mout = g_masks + (size_t)b*T_STEPS*32;

    for (int t = 0; t < T_STEPS; t++) {
        // 1. counts of active sr words
        unsigned myw = (tid < 32) ? s_srm[tid] : 0u;
        if (tid < 32) s_cnt[tid] = __popc(myw);
        __syncthreads();
        // 2. exclusive scan (warp 0)
        if (tid < 32) {
            int c = s_cnt[tid];
            int inc = c;
            #pragma unroll
            for (int d = 1; d < 32; d <<= 1) {
                int v = __shfl_up_sync(0xffffffffu, inc, d);
                if (lane >= d) inc += v;
            }
            s_off[tid] = inc - c;
            if (tid == 31) { s_tot = inc; s_n8 = (inc + 7) & ~7; }
        }
        __syncthreads();
        // 3. expand ballots into row list (ballot word v: h = (v>>2)*128 + l*4 + (v&3))
        if (tid < 32) {
            int o = s_off[tid];
            unsigned m = myw;
            int base = (tid >> 2)*128 + (tid & 3);
            while (m) {
                int l = __ffs(m) - 1; m &= m - 1;
                list[o++] = (unsigned short)(base + l*4);
            }
        }
        for (int i = s_tot + tid; i < s_n8; i += 256) list[i] = (unsigned short)1024;
        __syncthreads();
        // 4. fp32 gather over active rows
        const int n8 = s_n8;
        float4 f4 = *(const float4*)(fbase + (size_t)t*BH);
        float a0 = f4.x + bi[0], a1 = f4.y + bi[1], a2 = f4.z + bi[2], a3 = f4.w + bi[3];
        for (int i = 0; i < n8; i += 8) {
            uint4 u = *(const uint4*)&list[i];
            int e0 = u.x & 0xffff, e1 = u.x >> 16;
            int e2 = u.y & 0xffff, e3 = u.y >> 16;
            int e4 = u.z & 0xffff, e5 = u.z >> 16;
            int e6 = u.w & 0xffff, e7 = u.w >> 16;
            float4 v0 = *(const float4*)(wp + (size_t)e0*HID);
            float4 v1 = *(const float4*)(wp + (size_t)e1*HID);
            float4 v2 = *(const float4*)(wp + (size_t)e2*HID);
            float4 v3 = *(const float4*)(wp + (size_t)e3*HID);
            float4 v4 = *(const float4*)(wp + (size_t)e4*HID);
            float4 v5 = *(const float4*)(wp + (size_t)e5*HID);
            float4 v6 = *(const float4*)(wp + (size_t)e6*HID);
            float4 v7 = *(const float4*)(wp + (size_t)e7*HID);
            a0 += ((v0.x + v1.x) + (v2.x + v3.x)) + ((v4.x + v5.x) + (v6.x + v7.x));
            a1 += ((v0.y + v1.y) + (v2.y + v3.y)) + ((v4.y + v5.y) + (v6.y + v7.y));
            a2 += ((v0.z + v1.z) + (v2.z + v3.z)) + ((v4.z + v5.z) + (v6.z + v7.z));
            a3 += ((v0.w + v1.w) + (v2.w + v3.w)) + ((v4.w + v5.w) + (v6.w + v7.w));
        }
        float x[4] = {a0, a1, a2, a3};
        // 5. adaptive LIF update (4 neurons)
        #pragma unroll
        for (int i = 0; i < 4; i++) {
            bb[i] = ro[i]*bb[i] + (1.0f - ro[i])*sp[i];
            float Bv = 0.01f + 1.8f*bb[i];
            mem[i] = al[i]*mem[i] + (1.0f - al[i])*x[i] - Bv*sp[i];
            sp[i] = (mem[i] - Bv > 0.0f) ? 1.0f : 0.0f;
        }
        // 6. ballots -> smem (next step) + global (readout)
        #pragma unroll
        for (int i = 0; i < 4; i++) {
            unsigned m = __ballot_sync(0xffffffffu, sp[i] != 0.0f);
            if (lane == 0) {
                s_srm[w*4 + i] = m;
                mout[t*32 + w*4 + i] = m;
            }
        }
        __syncthreads();
    }
}

// ---------------- K5: readout + log_softmax -----------------------------------
__global__ __launch_bounds__(256)
void k_readout(const float* __restrict__ b2, float* __restrict__ out) {
    __shared__ float red[256][NOUT];
    __shared__ float vals[NOUT];
    __shared__ float s_l;
    const int b = blockIdx.x, tid = threadIdx.x;
    float acc[NOUT] = {};
    if (tid < T_STEPS) {
        float sum[NOUT] = {};
        const unsigned* gm = g_masks + ((size_t)b*T_STEPS + tid)*32;
        for (int v = 0; v < 32; v++) {
            unsigned m = gm[v];
            int base = (v >> 2)*128 + (v & 3);
            while (m) {
                int l = __ffs(m) - 1; m &= m - 1;
                const float* w2 = &g_W2T[(base + l*4)*NOUT];
                #pragma unroll
                for (int o = 0; o < NOUT; o++) sum[o] += w2[o];
            }
        }
        const float* c = &g_ctab[tid*NOUT];
        #pragma unroll
        for (int o = 0; o < NOUT; o++) acc[o] = c[o]*sum[o];
    }
    #pragma unroll
    for (int o = 0; o < NOUT; o++) red[tid][o] = acc[o];
    __syncthreads();
    for (int s = 128; s > 0; s >>= 1) {
        if (tid < s)
            #pragma unroll
            for (int o = 0; o < NOUT; o++) red[tid][o] += red[tid + s][o];
        __syncthreads();
    }
    if (tid < NOUT)
        vals[tid] = (red[0][tid] + g_csum[tid]*b2[tid]) * (1.0f / (float)T_STEPS);
    __syncthreads();
    if (tid == 0) {
        float m = vals[0];
        for (int o = 1; o < NOUT; o++) m = fmaxf(m, vals[o]);
        float s = 0.0f;
        for (int o = 0; o < NOUT; o++) s += expf(vals[o] - m);
        s_l = m + logf(s);
    }
    __syncthreads();
    if (tid < NOUT) out[b*NOUT + tid] = vals[tid] - s_l;
}

// ---------------- launch -------------------------------------------------------
extern "C" void kernel_launch(void* const* d_in, const int* in_sizes, int n_in,
                              void* d_out, int out_size) {
    const float* X        = (const float*)d_in[0];
    const float* thr      = (const float*)d_in[1];
    const float* W1       = (const float*)d_in[2];
    const float* b1       = (const float*)d_in[3];
    const float* Wd       = (const float*)d_in[4];
    const float* bd       = (const float*)d_in[5];
    const float* Wr       = (const float*)d_in[6];
    const float* br       = (const float*)d_in[7];
    const float* W2       = (const float*)d_in[8];
    const float* b2       = (const float*)d_in[9];
    const float* tau_m1   = (const float*)d_in[10];
    const float* tau_adp1 = (const float*)d_in[11];
    const float* tau_m_r  = (const float*)d_in[12];
    const float* tau_adp_r= (const float*)d_in[13];
    const float* tau_m2   = (const float*)d_in[14];
    float* out = (float*)d_out;

    k_prep<<<(HID*HID + 255)/256, 256>>>(Wd, Wr, W2, tau_m2);
    k_in_gemm<<<dim3(HID/BN, NROWS/BM), 256>>>(X, thr, W1, b1);
    k_l1_scan<<<BH/256, 256>>>(tau_m1, tau_adp1);
    k_dgemm<<<dim3(200, 16), 128>>>();
    k_steps<<<BATCH, 256>>>(tau_m_r, tau_adp_r, bd, br);
    k_readout<<<BATCH, 256>>>(b2, out);
}

// round 9
// speedup vs baseline: 4.7194x; 1.0895x over previous
#include <cuda_runtime.h>
#include <cuda_bf16.h>
#include <math.h>

#define T_STEPS 200
#define BATCH   128
#define HID     1024
#define K_IN    120
#define NOUT    12
#define BH      (BATCH*HID)      // 131072
#define NROWS   (T_STEPS*BATCH)  // 25600

// ---------------- static device scratch (no allocations allowed) ------------
__device__ float          g_F[NROWS*HID];       // W1 drive, then overwritten by D = S1@Wd^T
__device__ float          g_WrT[1025*HID];      // Wr^T fp32 [h][j] + zero pad row
__device__ __nv_bfloat16  g_WdB[3][HID*HID];    // Wd 3-way bf16 split, [j][h] native layout
__device__ __nv_bfloat16  g_W1B[3][HID*128];    // W1 3-way bf16 split, [n][k] padded 120->128
__device__ float          g_W2T[HID*NOUT];
__device__ unsigned       g_m1[(size_t)BATCH*T_STEPS*32];    // layer-1 spike masks (h-linear)
__device__ unsigned       g_masks[(size_t)BATCH*T_STEPS*32]; // recurrent spike ballots
__device__ float          g_ctab[T_STEPS*NOUT];
__device__ float          g_csum[NOUT];

// ---------------- prep: Wr transpose, Wd/W1 3-split, W2T, tables -------------
__global__ __launch_bounds__(256)
void k_prep(const float* __restrict__ Wd, const float* __restrict__ Wr,
            const float* __restrict__ W1, const float* __restrict__ W2,
            const float* __restrict__ tau_m2) {
    int idx = blockIdx.x * 256 + threadIdx.x;
    if (idx < HID*HID) {
        int j = idx >> 10, h = idx & 1023;
        g_WrT[(size_t)h*HID + j] = Wr[idx];      // Wr^T[h][j]
        float w = Wd[idx];
        __nv_bfloat16 h1 = __float2bfloat16(w);
        float r1 = w - __bfloat162float(h1);
        __nv_bfloat16 h2 = __float2bfloat16(r1);
        float r2 = r1 - __bfloat162float(h2);
        __nv_bfloat16 h3 = __float2bfloat16(r2);
        g_WdB[0][idx] = h1;
        g_WdB[1][idx] = h2;
        g_WdB[2][idx] = h3;
    }
    if (idx < HID*128) {                         // W1 split, K padded to 128
        int n = idx >> 7, k = idx & 127;
        float w = (k < K_IN) ? W1[n*K_IN + k] : 0.0f;
        __nv_bfloat16 h1 = __float2bfloat16(w);
        float r1 = w - __bfloat162float(h1);
        __nv_bfloat16 h2 = __float2bfloat16(r1);
        float r2 = r1 - __bfloat162float(h2);
        __nv_bfloat16 h3 = __float2bfloat16(r2);
        g_W1B[0][idx] = h1;
        g_W1B[1][idx] = h2;
        g_W1B[2][idx] = h3;
    }
    if (idx < HID*NOUT) {
        int h = idx / NOUT, o = idx % NOUT;
        g_W2T[idx] = W2[o*HID + h];
    }
    if (idx < T_STEPS*NOUT) {
        int k = idx / NOUT, o = idx % NOUT;
        float a2 = expf(-1.0f / tau_m2[o]);
        g_ctab[idx] = 1.0f - powf(a2, (float)(T_STEPS - k));
    }
    if (idx < NOUT) {
        float a2 = expf(-1.0f / tau_m2[idx]);
        float s = 0.0f, p = 1.0f;
        for (int n = 1; n <= T_STEPS; n++) { p *= a2; s += p; }
        g_csum[idx] = (float)T_STEPS - s;
    }
    if (idx < HID) g_WrT[(size_t)1024*HID + idx] = 0.0f;   // zero pad row
}

// ---------------- shared mma helpers ------------------------------------------
__device__ __forceinline__ void mma16816(float* c, const unsigned* a, unsigned b0, unsigned b1) {
    asm volatile("mma.sync.aligned.m16n8k16.row.col.f32.bf16.bf16.f32 "
        "{%0,%1,%2,%3}, {%4,%5,%6,%7}, {%8,%9}, {%0,%1,%2,%3};"
        : "+f"(c[0]), "+f"(c[1]), "+f"(c[2]), "+f"(c[3])
        : "r"(a[0]), "r"(a[1]), "r"(a[2]), "r"(a[3]), "r"(b0), "r"(b1));
}
__device__ __forceinline__ unsigned spike_pack(unsigned m, int c) {
    return (((m >> c) & 1u) ? 0x3F80u : 0u) | (((m >> (c+1)) & 1u) ? 0x3F800000u : 0u);
}
__device__ __forceinline__ void cp16(unsigned dst, const void* src) {
    asm volatile("cp.async.cg.shared.global [%0], [%1], 16;" :: "r"(dst), "l"(src) : "memory");
}

// ---------------- K1: F = ternary(X) @ W1^T + b1 via mma (bf16 3-split) -------
// grid (200 timesteps, 16 n-tiles of 64), 128 threads.
// warps: wm = w&1 (64 rows=b), wn = w>>1 (32 cols); mf=4, nf=4; K=128 in 4 chunks.
__global__ __launch_bounds__(128, 3)
void k_in_mma(const float* __restrict__ X, const float* __restrict__ thrp,
              const float* __restrict__ b1) {
    __shared__ unsigned short As[128][40];   // [b][32 cols + pad] (20-word stride)
    __shared__ unsigned Bs[2][3][64][20];    // double buffer, pad-20 conflict-free
    const int tid = threadIdx.x, lane = tid & 31, w = tid >> 5;
    const int wm = w & 1, wn = w >> 1;
    const int tt = blockIdx.x, Nb = blockIdx.y * 64;
    const int r = lane >> 2, t4 = lane & 3;
    const float thr = __ldg(thrp);
    float acc[4][4][4] = {};

    const uint4* w1b4 = (const uint4*)g_W1B;           // [s][n][16 uint4]
    const unsigned sbB = (unsigned)__cvta_generic_to_shared(Bs);

    auto stageB = [&](int kc, int buf) {
        #pragma unroll
        for (int i = tid; i < 768; i += 128) {         // 6 cp.async of 16B per thread
            int s = i >> 8, rem = i & 255, n = rem >> 2, kq = rem & 3;
            unsigned dst = sbB + (unsigned)((((buf*3 + s)*64 + n)*20 + kq*4)*4);
            cp16(dst, w1b4 + (size_t)s*16384 + (size_t)(Nb + n)*16 + kc*4 + kq);
        }
        asm volatile("cp.async.commit_group;" ::: "memory");
    };
    stageB(0, 0);

    for (int kc = 0; kc < 4; kc++) {
        // stage A chunk: ternarize X into As[b][0..31] (safe: prev compute synced)
        {
            int kk = kc*32 + lane;
            int c = kk / 40, f = kk - c*40;
            bool ok = kk < K_IN;
            size_t base = (size_t)c*8000 + (size_t)tt*40 + f;
            for (int b = w; b < 128; b += 4) {
                float xv = ok ? __ldg(X + (size_t)b*24000 + base) : 0.0f;
                unsigned short v = (xv > thr) ? (unsigned short)0x3F80
                                 : ((xv < -thr) ? (unsigned short)0xBF80 : (unsigned short)0);
                As[b][lane] = v;
            }
        }
        asm volatile("cp.async.wait_group 0;" ::: "memory");
        __syncthreads();                               // B(kc) ready, A visible
        if (kc < 3) stageB(kc + 1, (kc + 1) & 1);

        const int buf = kc & 1;
        const unsigned* AsW = (const unsigned*)As;     // word view, row stride 20
        #pragma unroll
        for (int e = 0; e < 2; e++) {
            unsigned a[4][4];
            #pragma unroll
            for (int mf = 0; mf < 4; mf++) {
                int row0 = wm*64 + mf*16 + r;
                a[mf][0] = AsW[row0*20       + e*8 + t4];
                a[mf][1] = AsW[(row0 + 8)*20 + e*8 + t4];
                a[mf][2] = AsW[row0*20       + e*8 + t4 + 4];
                a[mf][3] = AsW[(row0 + 8)*20 + e*8 + t4 + 4];
            }
            #pragma unroll
            for (int s = 0; s < 3; s++)
                #pragma unroll
                for (int nf = 0; nf < 4; nf++) {
                    const unsigned* brow = Bs[buf][s][wn*32 + nf*8 + r];
                    unsigned b0 = brow[e*8 + t4];
                    unsigned b1v = brow[e*8 + t4 + 4];
                    #pragma unroll
                    for (int mf = 0; mf < 4; mf++)
                        mma16816(acc[mf][nf], a[mf], b0, b1v);
                }
        }
        __syncthreads();                               // compute done before A overwrite
    }
    // epilogue: add bias, store F rows tt*128 + b
    #pragma unroll
    for (int nf = 0; nf < 4; nf++) {
        int col = Nb + wn*32 + nf*8 + t4*2;
        float2 bia = *(const float2*)&b1[col];
        #pragma unroll
        for (int mf = 0; mf < 4; mf++) {
            int row = tt*128 + wm*64 + mf*16 + r;
            *(float2*)&g_F[(size_t)row*HID + col] =
                make_float2(acc[mf][nf][0] + bia.x, acc[mf][nf][1] + bia.y);
            *(float2*)&g_F[(size_t)(row + 8)*HID + col] =
                make_float2(acc[mf][nf][2] + bia.x, acc[mf][nf][3] + bia.y);
        }
    }
}

// ---------------- K2: layer-1 LIF scan -> h-linear spike bitmasks -------------
__global__ __launch_bounds__(256)
void k_l1_scan(const float* __restrict__ tau_m1, const float* __restrict__ tau_adp1) {
    int idx = blockIdx.x * 256 + threadIdx.x;    // b*1024 + h
    int h = idx & 1023, b = idx >> 10;
    float alpha = expf(-1.0f / tau_m1[h]);
    float ro    = expf(-1.0f / tau_adp1[h]);
    float mem = 0.0f, spk = 0.0f, bb = 0.01f;
    int word = (h >> 5) & 31;
    int lane = threadIdx.x & 31;
    const float* f = g_F + idx;
    unsigned* mo = g_m1 + (size_t)b*T_STEPS*32 + word;
    for (int t0 = 0; t0 < T_STEPS; t0 += 8) {
        float x[8];
        #pragma unroll
        for (int i = 0; i < 8; i++) x[i] = __ldg(f + (size_t)(t0 + i)*BH);
        #pragma unroll
        for (int i = 0; i < 8; i++) {
            bb = ro*bb + (1.0f - ro)*spk;
            float Bv = 0.01f + 1.8f*bb;
            mem = alpha*mem + (1.0f - alpha)*x[i] - Bv*spk;
            spk = (mem - Bv > 0.0f) ? 1.0f : 0.0f;
            unsigned m = __ballot_sync(0xffffffffu, spk != 0.0f);
            if (lane == 0) mo[(t0 + i)*32] = m;
        }
    }
}

// ---------------- K3: D = S1 @ Wd^T via mma.sync bf16 3-split -----------------
// grid (200 m-tiles of 128 = one timestep, 16 n-tiles of 64), 128 threads.
__global__ __launch_bounds__(128, 3)
void k_dgemm() {
    __shared__ unsigned Bs[2][3][64][20];   // double buffer, pad-20 conflict-free
    const int tid = threadIdx.x, lane = tid & 31, w = tid >> 5;
    const int wm = w & 1, wn = w >> 1;
    const int tt = blockIdx.x, Nb = blockIdx.y * 64;   // M-tile = timestep tt
    const int r = lane >> 2, t4 = lane & 3;
    float acc[4][4][4] = {};             // [m-frag][n-frag][reg]

    const uint4* wdb4 = (const uint4*)g_WdB;
    const unsigned sb = (unsigned)__cvta_generic_to_shared(Bs);

    // mask row pointers: rows b = wm*64 + mf*16 + r + q*8, all at timestep tt
    const unsigned* mp[4][2];
    #pragma unroll
    for (int mf = 0; mf < 4; mf++)
        #pragma unroll
        for (int q = 0; q < 2; q++) {
            int b = wm*64 + mf*16 + r + q*8;
            mp[mf][q] = g_m1 + ((size_t)b*T_STEPS + tt)*32;
        }

    auto stage = [&](int kc, int buf) {
        #pragma unroll
        for (int i = tid; i < 768; i += 128) {        // 6 cp.async of 16B per thread
            int s = i >> 8, rem = i & 255, n = rem >> 2, kq = rem & 3;
            unsigned dst = sb + (unsigned)((((buf*3 + s)*64 + n)*20 + kq*4)*4);
            cp16(dst, wdb4 + (size_t)s*131072 + (size_t)(Nb + n)*128 + kc*4 + kq);
        }
        asm volatile("cp.async.commit_group;" ::: "memory");
    };

    stage(0, 0);
    unsigned mk[4][2];
    #pragma unroll
    for (int mf = 0; mf < 4; mf++) {
        mk[mf][0] = __ldg(&mp[mf][0][0]);
        mk[mf][1] = __ldg(&mp[mf][1][0]);
    }

    for (int kc = 0; kc < 32; kc++) {
        asm volatile("cp.async.wait_group 0;" ::: "memory");
        __syncthreads();                               // buf[kc&1] ready, prior reads done
        if (kc < 31) stage(kc + 1, (kc + 1) & 1);      // fills other buffer during compute

        unsigned mkn[4][2];
        if (kc < 31) {
            #pragma unroll
            for (int mf = 0; mf < 4; mf++) {
                mkn[mf][0] = __ldg(&mp[mf][0][kc + 1]);
                mkn[mf][1] = __ldg(&mp[mf][1][kc + 1]);
            }
        }

        const int buf = kc & 1;
        #pragma unroll
        for (int e = 0; e < 2; e++) {                  // two k16 halves of the 32-chunk
            const int cb = e*16 + t4*2;
            unsigned a[4][4];
            #pragma unroll
            for (int mf = 0; mf < 4; mf++) {
                a[mf][0] = spike_pack(mk[mf][0], cb);
                a[mf][1] = spike_pack(mk[mf][1], cb);
                a[mf][2] = spike_pack(mk[mf][0], cb + 8);
                a[mf][3] = spike_pack(mk[mf][1], cb + 8);
            }
            #pragma unroll
            for (int s = 0; s < 3; s++)
                #pragma unroll
                for (int nf = 0; nf < 4; nf++) {
                    const unsigned* brow = Bs[buf][s][wn*32 + nf*8 + r];
                    unsigned b0 = brow[e*8 + t4];
                    unsigned b1 = brow[e*8 + t4 + 4];
                    #pragma unroll
                    for (int mf = 0; mf < 4; mf++)
                        mma16816(acc[mf][nf], a[mf], b0, b1);
                }
        }
        #pragma unroll
        for (int mf = 0; mf < 4; mf++) {
            mk[mf][0] = mkn[mf][0];
            mk[mf][1] = mkn[mf][1];
        }
    }
    // epilogue: D rows (tt*128 + b) match g_F layout
    #pragma unroll
    for (int mf = 0; mf < 4; mf++)
        #pragma unroll
        for (int nf = 0; nf < 4; nf++) {
            int col = Nb + wn*32 + nf*8 + t4*2;
            int row = tt*128 + wm*64 + mf*16 + r;
            *(float2*)&g_F[(size_t)row*HID + col] =
                make_float2(acc[mf][nf][0], acc[mf][nf][1]);
            *(float2*)&g_F[(size_t)(row + 8)*HID + col] =
                make_float2(acc[mf][nf][2], acc[mf][nf][3]);
        }
}

// ---------------- K4: persistent recurrent loop (1 block per batch) -----------
__global__ __launch_bounds__(256)
void k_steps(const float* __restrict__ tau_m_r, const float* __restrict__ tau_adp_r,
             const float* __restrict__ bd, const float* __restrict__ br) {
    __shared__ unsigned s_srm[32];
    __shared__ __align__(16) unsigned short list[1032];
    __shared__ int s_cnt[32];
    __shared__ int s_off[32];
    __shared__ int s_tot, s_n8;
    const int b = blockIdx.x, tid = threadIdx.x;
    const int lane = tid & 31, w = tid >> 5;
    const int j0 = tid * 4;

    float al[4], ro[4], bi[4], mem[4], bb[4], sp[4];
    #pragma unroll
    for (int i = 0; i < 4; i++) {
        al[i] = expf(-1.0f / tau_m_r[j0 + i]);
        ro[i] = expf(-1.0f / tau_adp_r[j0 + i]);
        bi[i] = bd[j0 + i] + br[j0 + i];
        mem[i] = 0.0f; bb[i] = 0.01f; sp[i] = 0.0f;
    }
    if (tid < 32) s_srm[tid] = 0u;
    __syncthreads();

    const float* wp = g_WrT + j0;                       // float4 slice per thread
    const float* fbase = g_F + (size_t)b*HID + j0;
    unsigned* mout = g_masks + (size_t)b*T_STEPS*32;

    for (int t = 0; t < T_STEPS; t++) {
        // 1. counts of active sr words
        unsigned myw = (tid < 32) ? s_srm[tid] : 0u;
        if (tid < 32) s_cnt[tid] = __popc(myw);
        __syncthreads();
        // 2. exclusive scan (warp 0)
        if (tid < 32) {
            int c = s_cnt[tid];
            int inc = c;
            #pragma unroll
            for (int d = 1; d < 32; d <<= 1) {
                int v = __shfl_up_sync(0xffffffffu, inc, d);
                if (lane >= d) inc += v;
            }
            s_off[tid] = inc - c;
            if (tid == 31) { s_tot = inc; s_n8 = (inc + 7) & ~7; }
        }
        __syncthreads();
        // 3. expand ballots into row list (ballot word v: h = (v>>2)*128 + l*4 + (v&3))
        if (tid < 32) {
            int o = s_off[tid];
            unsigned m = myw;
            int base = (tid >> 2)*128 + (tid & 3);
            while (m) {
                int l = __ffs(m) - 1; m &= m - 1;
                list[o++] = (unsigned short)(base + l*4);
            }
        }
        for (int i = s_tot + tid; i < s_n8; i += 256) list[i] = (unsigned short)1024;
        __syncthreads();
        // 4. fp32 gather over active rows
        const int n8 = s_n8;
        float4 f4 = *(const float4*)(fbase + (size_t)t*BH);
        float a0 = f4.x + bi[0], a1 = f4.y + bi[1], a2 = f4.z + bi[2], a3 = f4.w + bi[3];
        for (int i = 0; i < n8; i += 8) {
            uint4 u = *(const uint4*)&list[i];
            int e0 = u.x & 0xffff, e1 = u.x >> 16;
            int e2 = u.y & 0xffff, e3 = u.y >> 16;
            int e4 = u.z & 0xffff, e5 = u.z >> 16;
            int e6 = u.w & 0xffff, e7 = u.w >> 16;
            float4 v0 = *(const float4*)(wp + (size_t)e0*HID);
            float4 v1 = *(const float4*)(wp + (size_t)e1*HID);
            float4 v2 = *(const float4*)(wp + (size_t)e2*HID);
            float4 v3 = *(const float4*)(wp + (size_t)e3*HID);
            float4 v4 = *(const float4*)(wp + (size_t)e4*HID);
            float4 v5 = *(const float4*)(wp + (size_t)e5*HID);
            float4 v6 = *(const float4*)(wp + (size_t)e6*HID);
            float4 v7 = *(const float4*)(wp + (size_t)e7*HID);
            a0 += ((v0.x + v1.x) + (v2.x + v3.x)) + ((v4.x + v5.x) + (v6.x + v7.x));
            a1 += ((v0.y + v1.y) + (v2.y + v3.y)) + ((v4.y + v5.y) + (v6.y + v7.y));
            a2 += ((v0.z + v1.z) + (v2.z + v3.z)) + ((v4.z + v5.z) + (v6.z + v7.z));
            a3 += ((v0.w + v1.w) + (v2.w + v3.w)) + ((v4.w + v5.w) + (v6.w + v7.w));
        }
        float x[4] = {a0, a1, a2, a3};
        // 5. adaptive LIF update (4 neurons)
        #pragma unroll
        for (int i = 0; i < 4; i++) {
            bb[i] = ro[i]*bb[i] + (1.0f - ro[i])*sp[i];
            float Bv = 0.01f + 1.8f*bb[i];
            mem[i] = al[i]*mem[i] + (1.0f - al[i])*x[i] - Bv*sp[i];
            sp[i] = (mem[i] - Bv > 0.0f) ? 1.0f : 0.0f;
        }
        // 6. ballots -> smem (next step) + global (readout)
        #pragma unroll
        for (int i = 0; i < 4; i++) {
            unsigned m = __ballot_sync(0xffffffffu, sp[i] != 0.0f);
            if (lane == 0) {
                s_srm[w*4 + i] = m;
                mout[t*32 + w*4 + i] = m;
            }
        }
        __syncthreads();
    }
}

// ---------------- K5: readout + log_softmax -----------------------------------
__global__ __launch_bounds__(256)
void k_readout(const float* __restrict__ b2, float* __restrict__ out) {
    __shared__ float red[256][NOUT];
    __shared__ float vals[NOUT];
    __shared__ float s_l;
    const int b = blockIdx.x, tid = threadIdx.x;
    float acc[NOUT] = {};
    if (tid < T_STEPS) {
        float sum[NOUT] = {};
        const unsigned* gm = g_masks + ((size_t)b*T_STEPS + tid)*32;
        for (int v = 0; v < 32; v++) {
            unsigned m = gm[v];
            int base = (v >> 2)*128 + (v & 3);
            while (m) {
                int l = __ffs(m) - 1; m &= m - 1;
                const float* w2 = &g_W2T[(base + l*4)*NOUT];
                #pragma unroll
                for (int o = 0; o < NOUT; o++) sum[o] += w2[o];
            }
        }
        const float* c = &g_ctab[tid*NOUT];
        #pragma unroll
        for (int o = 0; o < NOUT; o++) acc[o] = c[o]*sum[o];
    }
    #pragma unroll
    for (int o = 0; o < NOUT; o++) red[tid][o] = acc[o];
    __syncthreads();
    for (int s = 128; s > 0; s >>= 1) {
        if (tid < s)
            #pragma unroll
            for (int o = 0; o < NOUT; o++) red[tid][o] += red[tid + s][o];
        __syncthreads();
    }
    if (tid < NOUT)
        vals[tid] = (red[0][tid] + g_csum[tid]*b2[tid]) * (1.0f / (float)T_STEPS);
    __syncthreads();
    if (tid == 0) {
        float m = vals[0];
        for (int o = 1; o < NOUT; o++) m = fmaxf(m, vals[o]);
        float s = 0.0f;
        for (int o = 0; o < NOUT; o++) s += expf(vals[o] - m);
        s_l = m + logf(s);
    }
    __syncthreads();
    if (tid < NOUT) out[b*NOUT + tid] = vals[tid] - s_l;
}

// ---------------- launch -------------------------------------------------------
extern "C" void kernel_launch(void* const* d_in, const int* in_sizes, int n_in,
                              void* d_out, int out_size) {
    const float* X        = (const float*)d_in[0];
    const float* thr      = (const float*)d_in[1];
    const float* W1       = (const float*)d_in[2];
    const float* b1       = (const float*)d_in[3];
    const float* Wd       = (const float*)d_in[4];
    const float* bd       = (const float*)d_in[5];
    const float* Wr       = (const float*)d_in[6];
    const float* br       = (const float*)d_in[7];
    const float* W2       = (const float*)d_in[8];
    const float* b2       = (const float*)d_in[9];
    const float* tau_m1   = (const float*)d_in[10];
    const float* tau_adp1 = (const float*)d_in[11];
    const float* tau_m_r  = (const float*)d_in[12];
    const float* tau_adp_r= (const float*)d_in[13];
    const float* tau_m2   = (const float*)d_in[14];
    float* out = (float*)d_out;

    k_prep<<<(HID*HID + 255)/256, 256>>>(Wd, Wr, W1, W2, tau_m2);
    k_in_mma<<<dim3(T_STEPS, 16), 128>>>(X, thr, b1);
    k_l1_scan<<<BH/256, 256>>>(tau_m1, tau_adp1);
    k_dgemm<<<dim3(T_STEPS, 16), 128>>>();
    k_steps<<<BATCH, 256>>>(tau_m_r, tau_adp_r, bd, br);
    k_readout<<<BATCH, 256>>>(b2, out);
}

// round 10
// speedup vs baseline: 5.5438x; 1.1747x over previous
#include <cuda_runtime.h>
#include <cuda_bf16.h>
#include <math.h>

#define T_STEPS 200
#define BATCH   128
#define HID     1024
#define K_IN    120
#define NOUT    12
#define BH      (BATCH*HID)      // 131072
#define NROWS   (T_STEPS*BATCH)  // 25600

// ---------------- static device scratch (no allocations allowed) ------------
__device__ float          g_F[NROWS*HID];       // W1 drive, then overwritten by D = S1@Wd^T
__device__ float          g_WrT[1025*HID];      // Wr^T fp32 [h][j] + zero pad row
__device__ __nv_bfloat16  g_WdB[3][HID*HID];    // Wd 3-way bf16 split, [j][h] native layout
__device__ __nv_bfloat16  g_W1B[3][HID*128];    // W1 3-way bf16 split, [n][k] padded 120->128
__device__ float          g_W2T[HID*NOUT];
__device__ unsigned       g_m1[(size_t)BATCH*T_STEPS*32];    // layer-1 spike masks (h-linear)
__device__ unsigned       g_masks[(size_t)BATCH*T_STEPS*32]; // recurrent spike ballots
__device__ float          g_ctab[T_STEPS*NOUT];
__device__ float          g_csum[NOUT];
__device__ int            g_done[T_STEPS];      // dgemm tile-completion counters

// ---------------- prep: Wr transpose, Wd/W1 3-split, W2T, tables, flags ------
__global__ __launch_bounds__(256)
void k_prep(const float* __restrict__ Wd, const float* __restrict__ Wr,
            const float* __restrict__ W1, const float* __restrict__ W2,
            const float* __restrict__ tau_m2) {
    int idx = blockIdx.x * 256 + threadIdx.x;
    if (idx < HID*HID) {
        int j = idx >> 10, h = idx & 1023;
        g_WrT[(size_t)h*HID + j] = Wr[idx];      // Wr^T[h][j]
        float w = Wd[idx];
        __nv_bfloat16 h1 = __float2bfloat16(w);
        float r1 = w - __bfloat162float(h1);
        __nv_bfloat16 h2 = __float2bfloat16(r1);
        float r2 = r1 - __bfloat162float(h2);
        __nv_bfloat16 h3 = __float2bfloat16(r2);
        g_WdB[0][idx] = h1;
        g_WdB[1][idx] = h2;
        g_WdB[2][idx] = h3;
    }
    if (idx < HID*128) {                         // W1 split, K padded to 128
        int n = idx >> 7, k = idx & 127;
        float w = (k < K_IN) ? W1[n*K_IN + k] : 0.0f;
        __nv_bfloat16 h1 = __float2bfloat16(w);
        float r1 = w - __bfloat162float(h1);
        __nv_bfloat16 h2 = __float2bfloat16(r1);
        float r2 = r1 - __bfloat162float(h2);
        __nv_bfloat16 h3 = __float2bfloat16(r2);
        g_W1B[0][idx] = h1;
        g_W1B[1][idx] = h2;
        g_W1B[2][idx] = h3;
    }
    if (idx < HID*NOUT) {
        int h = idx / NOUT, o = idx % NOUT;
        g_W2T[idx] = W2[o*HID + h];
    }
    if (idx < T_STEPS*NOUT) {
        int k = idx / NOUT, o = idx % NOUT;
        float a2 = expf(-1.0f / tau_m2[o]);
        g_ctab[idx] = 1.0f - powf(a2, (float)(T_STEPS - k));
    }
    if (idx < NOUT) {
        float a2 = expf(-1.0f / tau_m2[idx]);
        float s = 0.0f, p = 1.0f;
        for (int n = 1; n <= T_STEPS; n++) { p *= a2; s += p; }
        g_csum[idx] = (float)T_STEPS - s;
    }
    if (idx < HID) g_WrT[(size_t)1024*HID + idx] = 0.0f;   // zero pad row
    if (idx < T_STEPS) g_done[idx] = 0;                    // reset every launch
}

// ---------------- shared mma helpers ------------------------------------------
__device__ __forceinline__ void mma16816(float* c, const unsigned* a, unsigned b0, unsigned b1) {
    asm volatile("mma.sync.aligned.m16n8k16.row.col.f32.bf16.bf16.f32 "
        "{%0,%1,%2,%3}, {%4,%5,%6,%7}, {%8,%9}, {%0,%1,%2,%3};"
        : "+f"(c[0]), "+f"(c[1]), "+f"(c[2]), "+f"(c[3])
        : "r"(a[0]), "r"(a[1]), "r"(a[2]), "r"(a[3]), "r"(b0), "r"(b1));
}
__device__ __forceinline__ unsigned spike_pack(unsigned m, int c) {
    return (((m >> c) & 1u) ? 0x3F80u : 0u) | (((m >> (c+1)) & 1u) ? 0x3F800000u : 0u);
}
__device__ __forceinline__ void cp16(unsigned dst, const void* src) {
    asm volatile("cp.async.cg.shared.global [%0], [%1], 16;" :: "r"(dst), "l"(src) : "memory");
}
__device__ __forceinline__ float4 ldcg4(const float4* p) {
    float4 v;
    asm volatile("ld.global.cg.v4.f32 {%0,%1,%2,%3}, [%4];"
        : "=f"(v.x), "=f"(v.y), "=f"(v.z), "=f"(v.w) : "l"(p));
    return v;
}

// ---------------- K1: F = ternary(X) @ W1^T + b1 via mma (bf16 3-split) -------
__global__ __launch_bounds__(128, 3)
void k_in_mma(const float* __restrict__ X, const float* __restrict__ thrp,
              const float* __restrict__ b1) {
    __shared__ unsigned short As[128][40];
    __shared__ unsigned Bs[2][3][64][20];
    const int tid = threadIdx.x, lane = tid & 31, w = tid >> 5;
    const int wm = w & 1, wn = w >> 1;
    const int tt = blockIdx.x, Nb = blockIdx.y * 64;
    const int r = lane >> 2, t4 = lane & 3;
    const float thr = __ldg(thrp);
    float acc[4][4][4] = {};

    const uint4* w1b4 = (const uint4*)g_W1B;
    const unsigned sbB = (unsigned)__cvta_generic_to_shared(Bs);

    auto stageB = [&](int kc, int buf) {
        #pragma unroll
        for (int i = tid; i < 768; i += 128) {
            int s = i >> 8, rem = i & 255, n = rem >> 2, kq = rem & 3;
            unsigned dst = sbB + (unsigned)((((buf*3 + s)*64 + n)*20 + kq*4)*4);
            cp16(dst, w1b4 + (size_t)s*16384 + (size_t)(Nb + n)*16 + kc*4 + kq);
        }
        asm volatile("cp.async.commit_group;" ::: "memory");
    };
    stageB(0, 0);

    for (int kc = 0; kc < 4; kc++) {
        {
            int kk = kc*32 + lane;
            int c = kk / 40, f = kk - c*40;
            bool ok = kk < K_IN;
            size_t base = (size_t)c*8000 + (size_t)tt*40 + f;
            for (int b = w; b < 128; b += 4) {
                float xv = ok ? __ldg(X + (size_t)b*24000 + base) : 0.0f;
                unsigned short v = (xv > thr) ? (unsigned short)0x3F80
                                 : ((xv < -thr) ? (unsigned short)0xBF80 : (unsigned short)0);
                As[b][lane] = v;
            }
        }
        asm volatile("cp.async.wait_group 0;" ::: "memory");
        __syncthreads();
        if (kc < 3) stageB(kc + 1, (kc + 1) & 1);

        const int buf = kc & 1;
        const unsigned* AsW = (const unsigned*)As;
        #pragma unroll
        for (int e = 0; e < 2; e++) {
            unsigned a[4][4];
            #pragma unroll
            for (int mf = 0; mf < 4; mf++) {
                int row0 = wm*64 + mf*16 + r;
                a[mf][0] = AsW[row0*20       + e*8 + t4];
                a[mf][1] = AsW[(row0 + 8)*20 + e*8 + t4];
                a[mf][2] = AsW[row0*20       + e*8 + t4 + 4];
                a[mf][3] = AsW[(row0 + 8)*20 + e*8 + t4 + 4];
            }
            #pragma unroll
            for (int s = 0; s < 3; s++)
                #pragma unroll
                for (int nf = 0; nf < 4; nf++) {
                    const unsigned* brow = Bs[buf][s][wn*32 + nf*8 + r];
                    unsigned b0 = brow[e*8 + t4];
                    unsigned b1v = brow[e*8 + t4 + 4];
                    #pragma unroll
                    for (int mf = 0; mf < 4; mf++)
                        mma16816(acc[mf][nf], a[mf], b0, b1v);
                }
        }
        __syncthreads();
    }
    #pragma unroll
    for (int nf = 0; nf < 4; nf++) {
        int col = Nb + wn*32 + nf*8 + t4*2;
        float2 bia = *(const float2*)&b1[col];
        #pragma unroll
        for (int mf = 0; mf < 4; mf++) {
            int row = tt*128 + wm*64 + mf*16 + r;
            *(float2*)&g_F[(size_t)row*HID + col] =
                make_float2(acc[mf][nf][0] + bia.x, acc[mf][nf][1] + bia.y);
            *(float2*)&g_F[(size_t)(row + 8)*HID + col] =
                make_float2(acc[mf][nf][2] + bia.x, acc[mf][nf][3] + bia.y);
        }
    }
}

// ---------------- K2: layer-1 LIF scan -> h-linear spike bitmasks -------------
__global__ __launch_bounds__(256)
void k_l1_scan(const float* __restrict__ tau_m1, const float* __restrict__ tau_adp1) {
    int idx = blockIdx.x * 256 + threadIdx.x;    // b*1024 + h
    int h = idx & 1023, b = idx >> 10;
    float alpha = expf(-1.0f / tau_m1[h]);
    float ro    = expf(-1.0f / tau_adp1[h]);
    float mem = 0.0f, spk = 0.0f, bb = 0.01f;
    int word = (h >> 5) & 31;
    int lane = threadIdx.x & 31;
    const float* f = g_F + idx;
    unsigned* mo = g_m1 + (size_t)b*T_STEPS*32 + word;
    for (int t0 = 0; t0 < T_STEPS; t0 += 8) {
        float x[8];
        #pragma unroll
        for (int i = 0; i < 8; i++) x[i] = __ldg(f + (size_t)(t0 + i)*BH);
        #pragma unroll
        for (int i = 0; i < 8; i++) {
            bb = ro*bb + (1.0f - ro)*spk;
            float Bv = 0.01f + 1.8f*bb;
            mem = alpha*mem + (1.0f - alpha)*x[i] - Bv*spk;
            spk = (mem - Bv > 0.0f) ? 1.0f : 0.0f;
            unsigned m = __ballot_sync(0xffffffffu, spk != 0.0f);
            if (lane == 0) mo[(t0 + i)*32] = m;
        }
    }
}

// ---------------- K3: merged dgemm producer + recurrent-step consumer ---------
// grid = 128 step blocks (first) + 3200 dgemm blocks; 128 threads each.
struct StepS {
    unsigned srm[32];
    int cnt[32];
    int off[32];
    int tot, n4;
    unsigned short list[1040];
};
union SmU {
    unsigned dg[2][3][64][20];   // 30720 B dgemm double buffer
    StepS st;
};

__global__ __launch_bounds__(128, 3)
void k_main(const float* __restrict__ tau_m_r, const float* __restrict__ tau_adp_r,
            const float* __restrict__ bd, const float* __restrict__ br) {
    __shared__ __align__(16) SmU sm;
    const int tid = threadIdx.x, lane = tid & 31, w = tid >> 5;

    if (blockIdx.x >= 128) {
        // ================= dgemm role: D(tt) tile (Nb) =================
        const int ds = blockIdx.x - 128;
        const int tt = ds >> 4, Nb = (ds & 15) << 6;
        const int wm = w & 1, wn = w >> 1;
        const int r = lane >> 2, t4 = lane & 3;
        float acc[4][4][4] = {};

        const uint4* wdb4 = (const uint4*)g_WdB;
        const unsigned sb = (unsigned)__cvta_generic_to_shared(sm.dg);

        const unsigned* mp[4][2];
        #pragma unroll
        for (int mf = 0; mf < 4; mf++)
            #pragma unroll
            for (int q = 0; q < 2; q++) {
                int b = wm*64 + mf*16 + r + q*8;
                mp[mf][q] = g_m1 + ((size_t)b*T_STEPS + tt)*32;
            }

        auto stage = [&](int kc, int buf) {
            #pragma unroll
            for (int i = tid; i < 768; i += 128) {
                int s = i >> 8, rem = i & 255, n = rem >> 2, kq = rem & 3;
                unsigned dst = sb + (unsigned)((((buf*3 + s)*64 + n)*20 + kq*4)*4);
                cp16(dst, wdb4 + (size_t)s*131072 + (size_t)(Nb + n)*128 + kc*4 + kq);
            }
            asm volatile("cp.async.commit_group;" ::: "memory");
        };

        stage(0, 0);
        unsigned mk[4][2];
        #pragma unroll
        for (int mf = 0; mf < 4; mf++) {
            mk[mf][0] = __ldg(&mp[mf][0][0]);
            mk[mf][1] = __ldg(&mp[mf][1][0]);
        }

        for (int kc = 0; kc < 32; kc++) {
            asm volatile("cp.async.wait_group 0;" ::: "memory");
            __syncthreads();
            if (kc < 31) stage(kc + 1, (kc + 1) & 1);

            unsigned mkn[4][2];
            if (kc < 31) {
                #pragma unroll
                for (int mf = 0; mf < 4; mf++) {
                    mkn[mf][0] = __ldg(&mp[mf][0][kc + 1]);
                    mkn[mf][1] = __ldg(&mp[mf][1][kc + 1]);
                }
            }

            const int buf = kc & 1;
            #pragma unroll
            for (int e = 0; e < 2; e++) {
                const int cb = e*16 + t4*2;
                unsigned a[4][4];
                #pragma unroll
                for (int mf = 0; mf < 4; mf++) {
                    a[mf][0] = spike_pack(mk[mf][0], cb);
                    a[mf][1] = spike_pack(mk[mf][1], cb);
                    a[mf][2] = spike_pack(mk[mf][0], cb + 8);
                    a[mf][3] = spike_pack(mk[mf][1], cb + 8);
                }
                #pragma unroll
                for (int s = 0; s < 3; s++)
                    #pragma unroll
                    for (int nf = 0; nf < 4; nf++) {
                        const unsigned* brow = sm.dg[buf][s] [wn*32 + nf*8 + r];
                        unsigned b0 = brow[e*8 + t4];
                        unsigned b1 = brow[e*8 + t4 + 4];
                        #pragma unroll
                        for (int mf = 0; mf < 4; mf++)
                            mma16816(acc[mf][nf], a[mf], b0, b1);
                    }
            }
            #pragma unroll
            for (int mf = 0; mf < 4; mf++) {
                mk[mf][0] = mkn[mf][0];
                mk[mf][1] = mkn[mf][1];
            }
        }
        #pragma unroll
        for (int mf = 0; mf < 4; mf++)
            #pragma unroll
            for (int nf = 0; nf < 4; nf++) {
                int col = Nb + wn*32 + nf*8 + t4*2;
                int row = tt*128 + wm*64 + mf*16 + r;
                *(float2*)&g_F[(size_t)row*HID + col] =
                    make_float2(acc[mf][nf][0], acc[mf][nf][1]);
                *(float2*)&g_F[(size_t)(row + 8)*HID + col] =
                    make_float2(acc[mf][nf][2], acc[mf][nf][3]);
            }
        __threadfence();                 // each thread releases its stores
        __syncthreads();
        if (tid == 0) atomicAdd(&g_done[tt], 1);
        return;
    }

    // ================= step role: one batch sample, 8 neurons/thread ==========
    const int b = blockIdx.x;
    const int j0 = tid * 8;

    float al[8], ro[8], bi[8], mem[8], bb[8], sp[8];
    #pragma unroll
    for (int i = 0; i < 8; i++) {
        al[i] = expf(-1.0f / tau_m_r[j0 + i]);
        ro[i] = expf(-1.0f / tau_adp_r[j0 + i]);
        bi[i] = bd[j0 + i] + br[j0 + i];
        mem[i] = 0.0f; bb[i] = 0.01f; sp[i] = 0.0f;
    }
    if (tid < 32) sm.st.srm[tid] = 0u;
    __syncthreads();

    const float4* wp = (const float4*)(g_WrT + j0);      // 2 float4 per row
    const float4* fbase = (const float4*)(g_F + (size_t)b*HID + j0);
    unsigned* mout = g_masks + (size_t)b*T_STEPS*32;
    volatile int* done = g_done;

    for (int t = 0; t < T_STEPS; t++) {
        // 0. wait for D(t) tiles from dgemm role
        if (tid == 0) { while (done[t] < 16) { } }
        __syncthreads();
        // 1. counts of active sr words
        unsigned myw = (tid < 32) ? sm.st.srm[tid] : 0u;
        if (tid < 32) sm.st.cnt[tid] = __popc(myw);
        __syncthreads();
        // 2. exclusive scan (warp 0)
        if (tid < 32) {
            int c = sm.st.cnt[tid];
            int inc = c;
            #pragma unroll
            for (int d = 1; d < 32; d <<= 1) {
                int v = __shfl_up_sync(0xffffffffu, inc, d);
                if (lane >= d) inc += v;
            }
            sm.st.off[tid] = inc - c;
            if (tid == 31) { sm.st.tot = inc; sm.st.n4 = (inc + 3) & ~3; }
        }
        __syncthreads();
        // 3. expand ballots (word v: h = (v>>3)*256 + l*8 + (v&7))
        if (tid < 32) {
            int o = sm.st.off[tid];
            unsigned m = myw;
            int base = (tid >> 3)*256 + (tid & 7);
            while (m) {
                int l = __ffs(m) - 1; m &= m - 1;
                sm.st.list[o++] = (unsigned short)(base + l*8);
            }
        }
        for (int i = sm.st.tot + tid; i < sm.st.n4; i += 128)
            sm.st.list[i] = (unsigned short)1024;
        __syncthreads();
        // 4. fp32 gather over active rows (bypass L1 for F: produced this kernel)
        const int n4 = sm.st.n4;
        float4 fa = ldcg4(fbase + (size_t)t*(BH/4));
        float4 fb = ldcg4(fbase + (size_t)t*(BH/4) + 1);
        float a0 = fa.x + bi[0], a1 = fa.y + bi[1], a2 = fa.z + bi[2], a3 = fa.w + bi[3];
        float a4 = fb.x + bi[4], a5 = fb.y + bi[5], a6 = fb.z + bi[6], a7 = fb.w + bi[7];
        for (int i = 0; i < n4; i += 4) {
            uint2 u = *(const uint2*)&sm.st.list[i];
            int e0 = u.x & 0xffff, e1 = u.x >> 16;
            int e2 = u.y & 0xffff, e3 = u.y >> 16;
            float4 v0a = __ldg(wp + (size_t)e0*(HID/4)), v0b = __ldg(wp + (size_t)e0*(HID/4) + 1);
            float4 v1a = __ldg(wp + (size_t)e1*(HID/4)), v1b = __ldg(wp + (size_t)e1*(HID/4) + 1);
            float4 v2a = __ldg(wp + (size_t)e2*(HID/4)), v2b = __ldg(wp + (size_t)e2*(HID/4) + 1);
            float4 v3a = __ldg(wp + (size_t)e3*(HID/4)), v3b = __ldg(wp + (size_t)e3*(HID/4) + 1);
            a0 += (v0a.x + v1a.x) + (v2a.x + v3a.x);
            a1 += (v0a.y + v1a.y) + (v2a.y + v3a.y);
            a2 += (v0a.z + v1a.z) + (v2a.z + v3a.z);
            a3 += (v0a.w + v1a.w) + (v2a.w + v3a.w);
            a4 += (v0b.x + v1b.x) + (v2b.x + v3b.x);
            a5 += (v0b.y + v1b.y) + (v2b.y + v3b.y);
            a6 += (v0b.z + v1b.z) + (v2b.z + v3b.z);
            a7 += (v0b.w + v1b.w) + (v2b.w + v3b.w);
        }
        float x[8] = {a0, a1, a2, a3, a4, a5, a6, a7};
        // 5. adaptive LIF update (8 neurons)
        #pragma unroll
        for (int i = 0; i < 8; i++) {
            bb[i] = ro[i]*bb[i] + (1.0f - ro[i])*sp[i];
            float Bv = 0.01f + 1.8f*bb[i];
            mem[i] = al[i]*mem[i] + (1.0f - al[i])*x[i] - Bv*sp[i];
            sp[i] = (mem[i] - Bv > 0.0f) ? 1.0f : 0.0f;
        }
        __syncthreads();                  // list fully consumed before overwrite
        // 6. ballots -> smem (next step) + global (readout)
        #pragma unroll
        for (int i = 0; i < 8; i++) {
            unsigned m = __ballot_sync(0xffffffffu, sp[i] != 0.0f);
            if (lane == 0) {
                sm.st.srm[w*8 + i] = m;
                mout[t*32 + w*8 + i] = m;
            }
        }
        __syncthreads();
    }
}

// ---------------- K4: readout + log_softmax -----------------------------------
__global__ __launch_bounds__(256)
void k_readout(const float* __restrict__ b2, float* __restrict__ out) {
    __shared__ float red[256][NOUT];
    __shared__ float vals[NOUT];
    __shared__ float s_l;
    const int b = blockIdx.x, tid = threadIdx.x;
    float acc[NOUT] = {};
    if (tid < T_STEPS) {
        float sum[NOUT] = {};
        const unsigned* gm = g_masks + ((size_t)b*T_STEPS + tid)*32;
        for (int v = 0; v < 32; v++) {
            unsigned m = gm[v];
            int base = (v >> 3)*256 + (v & 7);
            while (m) {
                int l = __ffs(m) - 1; m &= m - 1;
                const float* w2 = &g_W2T[(base + l*8)*NOUT];
                #pragma unroll
                for (int o = 0; o < NOUT; o++) sum[o] += w2[o];
            }
        }
        const float* c = &g_ctab[tid*NOUT];
        #pragma unroll
        for (int o = 0; o < NOUT; o++) acc[o] = c[o]*sum[o];
    }
    #pragma unroll
    for (int o = 0; o < NOUT; o++) red[tid][o] = acc[o];
    __syncthreads();
    for (int s = 128; s > 0; s >>= 1) {
        if (tid < s)
            #pragma unroll
            for (int o = 0; o < NOUT; o++) red[tid][o] += red[tid + s][o];
        __syncthreads();
    }
    if (tid < NOUT)
        vals[tid] = (red[0][tid] + g_csum[tid]*b2[tid]) * (1.0f / (float)T_STEPS);
    __syncthreads();
    if (tid == 0) {
        float m = vals[0];
        for (int o = 1; o < NOUT; o++) m = fmaxf(m, vals[o]);
        float s = 0.0f;
        for (int o = 0; o < NOUT; o++) s += expf(vals[o] - m);
        s_l = m + logf(s);
    }
    __syncthreads();
    if (tid < NOUT) out[b*NOUT + tid] = vals[tid] - s_l;
}

// ---------------- launch -------------------------------------------------------
extern "C" void kernel_launch(void* const* d_in, const int* in_sizes, int n_in,
                              void* d_out, int out_size) {
    const float* X        = (const float*)d_in[0];
    const float* thr      = (const float*)d_in[1];
    const float* W1       = (const float*)d_in[2];
    const float* b1       = (const float*)d_in[3];
    const float* Wd       = (const float*)d_in[4];
    const float* bd       = (const float*)d_in[5];
    const float* Wr       = (const float*)d_in[6];
    const float* br       = (const float*)d_in[7];
    const float* W2       = (const float*)d_in[8];
    const float* b2       = (const float*)d_in[9];
    const float* tau_m1   = (const float*)d_in[10];
    const float* tau_adp1 = (const float*)d_in[11];
    const float* tau_m_r  = (const float*)d_in[12];
    const float* tau_adp_r= (const float*)d_in[13];
    const float* tau_m2   = (const float*)d_in[14];
    float* out = (float*)d_out;

    k_prep<<<(HID*HID + 255)/256, 256>>>(Wd, Wr, W1, W2, tau_m2);
    k_in_mma<<<dim3(T_STEPS, 16), 128>>>(X, thr, b1);
    k_l1_scan<<<BH/256, 256>>>(tau_m1, tau_adp1);
    k_main<<<128 + T_STEPS*16, 128>>>(tau_m_r, tau_adp_r, bd, br);
    k_readout<<<BATCH, 256>>>(b2, out);
}